// round 12
// baseline (speedup 1.0000x reference)
#include <cuda_runtime.h>
#include <math.h>

#define IN_CH   64
#define MID     128      // OUT_CH*HEADS
#define GH      256      // HEADS*IN_CH (gate hidden)
#define HEADS   4
#define SEGS    1024
#define MAXN    500000
#define MAXLOC  8

// scratch (static device globals — no runtime allocation)
__device__ float g_gate[(size_t)MAXN * HEADS];   // 8 MB
__device__ float g_denom[SEGS * HEADS];

// ------------------------------------------------------------------
// init: zero output accumulator and denominators
// ------------------------------------------------------------------
__global__ void k_init(float* __restrict__ out) {
    int i = blockIdx.x * blockDim.x + threadIdx.x;
    if (i < SEGS * MID)   out[i] = 0.f;
    if (i < SEGS * HEADS) g_denom[i] = 0.f;
}

// ------------------------------------------------------------------
// Pass A: gate[N,4] = prelu(x @ gw1^T) @ gw2^T
// block = 64 nodes, 256 threads, C tile [64 x 256] (8x8 micro per thread)
// smem: xs[64][65] | w1[256][65] | w2[4*256]
// ------------------------------------------------------------------
#define A_SMEM_FLOATS (64*65 + 256*65 + 1024)
__global__ __launch_bounds__(256) void k_gate(
    const float* __restrict__ x, const float* __restrict__ gw1,
    const float* __restrict__ gw2, const float* __restrict__ prelu_a, int n)
{
    extern __shared__ float sm[];
    float* xs  = sm;                    // 64*65 = 4160
    float* w1s = sm + 4160;             // 256*65 = 16640
    float* w2s = sm + 4160 + 16640;     // 1024

    int tid = threadIdx.x;
    int m0  = blockIdx.x * 64;

    {   // x tile (zero padded)
        const float4* x4 = (const float4*)x;
        #pragma unroll
        for (int t = 0; t < 4; ++t) {
            int fid = tid + t * 256;            // < 1024
            int m = fid >> 4, k4 = fid & 15;
            float4 v = make_float4(0.f, 0.f, 0.f, 0.f);
            if (m0 + m < n) v = x4[(size_t)(m0 + m) * 16 + k4];
            float* d = &xs[m * 65 + k4 * 4];
            d[0] = v.x; d[1] = v.y; d[2] = v.z; d[3] = v.w;
        }
        const float4* w14 = (const float4*)gw1;
        #pragma unroll
        for (int t = 0; t < 16; ++t) {
            int fid = tid + t * 256;            // < 4096
            int c = fid >> 4, k4 = fid & 15;
            float4 v = w14[fid];
            float* d = &w1s[c * 65 + k4 * 4];
            d[0] = v.x; d[1] = v.y; d[2] = v.z; d[3] = v.w;
        }
        ((float4*)w2s)[tid] = ((const float4*)gw2)[tid];  // 256 float4 = 1024 f
    }
    __syncthreads();

    int rg = tid >> 5, cg = tid & 31;   // warp = one row-group, lanes span cols
    int r0 = rg * 8, c0 = cg * 4;

    float acc[8][8];
    #pragma unroll
    for (int i = 0; i < 8; ++i)
        #pragma unroll
        for (int j = 0; j < 8; ++j) acc[i][j] = 0.f;

    #pragma unroll 8
    for (int k = 0; k < 64; ++k) {
        float a[8], b[8];
        #pragma unroll
        for (int i = 0; i < 8; ++i) a[i] = xs[(r0 + i) * 65 + k];
        #pragma unroll
        for (int j = 0; j < 4; ++j) {
            b[j]     = w1s[(c0 + j) * 65 + k];
            b[4 + j] = w1s[(128 + c0 + j) * 65 + k];
        }
        #pragma unroll
        for (int i = 0; i < 8; ++i)
            #pragma unroll
            for (int j = 0; j < 8; ++j)
                acc[i][j] = fmaf(a[i], b[j], acc[i][j]);
    }

    // PReLU + project onto 4 heads (per-lane partials over this lane's 8 cols)
    float slope = *prelu_a;
    float p[32];
    #pragma unroll
    for (int v = 0; v < 32; ++v) p[v] = 0.f;
    #pragma unroll
    for (int j = 0; j < 8; ++j) {
        int col = (j < 4) ? (c0 + j) : (128 + c0 + j - 4);
        float w0 = w2s[0 * 256 + col], w1v = w2s[1 * 256 + col];
        float w2v = w2s[2 * 256 + col], w3 = w2s[3 * 256 + col];
        #pragma unroll
        for (int i = 0; i < 8; ++i) {
            float h = acc[i][j];
            h = (h >= 0.f) ? h : slope * h;
            p[i * 4 + 0] = fmaf(h, w0,  p[i * 4 + 0]);
            p[i * 4 + 1] = fmaf(h, w1v, p[i * 4 + 1]);
            p[i * 4 + 2] = fmaf(h, w2v, p[i * 4 + 2]);
            p[i * 4 + 3] = fmaf(h, w3,  p[i * 4 + 3]);
        }
    }
    // warp allreduce of the 32 (node,head) partials
    #pragma unroll
    for (int s = 16; s > 0; s >>= 1)
        #pragma unroll
        for (int v = 0; v < 32; ++v)
            p[v] += __shfl_xor_sync(0xffffffffu, p[v], s);

    // lane l owns value l = i*4+h  (static select keeps p in registers)
    float myval = 0.f;
    #pragma unroll
    for (int v = 0; v < 32; ++v) myval = (v == cg) ? p[v] : myval;
    int i = cg >> 2, h = cg & 3;
    int node = m0 + r0 + i;
    if (node < n) g_gate[(size_t)node * 4 + h] = myval;
}

// ------------------------------------------------------------------
// Pass B: feat = relu(x@mw1^T + b1)@mw2^T + b2 ; w = exp(gate)
//         segmented accumulate  out += w*feat,  denom += w
// block = 128 nodes, 256 threads, C tile [128 x 128]
// ------------------------------------------------------------------
#define B_SMEM_FLOATS (128*65 + 128*65 + 128*129 + 128*129 + 8*128 + 32 + 128)
__global__ __launch_bounds__(256) void k_feat(
    const float* __restrict__ x, const int* __restrict__ batch,
    const float* __restrict__ mw1, const float* __restrict__ mb1,
    const float* __restrict__ mw2, const float* __restrict__ mb2,
    float* __restrict__ out, int n)
{
    extern __shared__ float sm[];
    float* xs  = sm;                    // 128*65  = 8320
    float* w1s = sm + 8320;             // 128*65  = 8320
    float* w2s = sm + 16640;            // 128*129 = 16512
    float* t1s = sm + 33152;            // 128*129 = 16512
    float* oac = sm + 49664;            // 8*128   = 1024
    float* dac = sm + 50688;            // 32
    int*  sbat = (int*)(sm + 50720);    // 128 ints

    int tid = threadIdx.x;
    int m0  = blockIdx.x * 128;

    {   // loads
        const float4* x4 = (const float4*)x;
        #pragma unroll
        for (int t = 0; t < 8; ++t) {
            int fid = tid + t * 256;            // < 2048
            int m = fid >> 4, k4 = fid & 15;
            float4 v = make_float4(0.f, 0.f, 0.f, 0.f);
            if (m0 + m < n) v = x4[(size_t)(m0 + m) * 16 + k4];
            float* d = &xs[m * 65 + k4 * 4];
            d[0] = v.x; d[1] = v.y; d[2] = v.z; d[3] = v.w;
        }
        const float4* w14 = (const float4*)mw1;
        #pragma unroll
        for (int t = 0; t < 8; ++t) {
            int fid = tid + t * 256;            // < 2048
            int c = fid >> 4, k4 = fid & 15;
            float4 v = w14[fid];
            float* d = &w1s[c * 65 + k4 * 4];
            d[0] = v.x; d[1] = v.y; d[2] = v.z; d[3] = v.w;
        }
        const float4* w24 = (const float4*)mw2;
        #pragma unroll
        for (int t = 0; t < 16; ++t) {
            int fid = tid + t * 256;            // < 4096
            int c = fid >> 5, k8 = fid & 31;
            float4 v = w24[fid];
            float* d = &w2s[c * 129 + k8 * 4];
            d[0] = v.x; d[1] = v.y; d[2] = v.z; d[3] = v.w;
        }
        if (tid < 128) sbat[tid] = (m0 + tid < n) ? batch[m0 + tid] : -1;
        for (int i = tid; i < 8 * 128; i += 256) oac[i] = 0.f;
        if (tid < 32) dac[tid] = 0.f;
    }
    __syncthreads();

    int rg = tid >> 4, cg = tid & 15;   // warp = 2 row-groups x 16 col-groups
    int r0 = rg * 8, c0 = cg * 4;

    float acc[8][8];
    #pragma unroll
    for (int i = 0; i < 8; ++i)
        #pragma unroll
        for (int j = 0; j < 8; ++j) acc[i][j] = 0.f;

    // GEMM1: t1 = relu(x @ mw1^T + b1), K = 64
    #pragma unroll 8
    for (int k = 0; k < 64; ++k) {
        float a[8], b[8];
        #pragma unroll
        for (int i = 0; i < 8; ++i) a[i] = xs[(r0 + i) * 65 + k];
        #pragma unroll
        for (int j = 0; j < 4; ++j) {
            b[j]     = w1s[(c0 + j) * 65 + k];
            b[4 + j] = w1s[(64 + c0 + j) * 65 + k];
        }
        #pragma unroll
        for (int i = 0; i < 8; ++i)
            #pragma unroll
            for (int j = 0; j < 8; ++j)
                acc[i][j] = fmaf(a[i], b[j], acc[i][j]);
    }
    {   // bias + relu -> t1s
        float b1a[8];
        #pragma unroll
        for (int j = 0; j < 4; ++j) { b1a[j] = mb1[c0 + j]; b1a[4 + j] = mb1[64 + c0 + j]; }
        #pragma unroll
        for (int i = 0; i < 8; ++i)
            #pragma unroll
            for (int j = 0; j < 8; ++j) {
                float v = acc[i][j] + b1a[j];
                v = fmaxf(v, 0.f);
                int col = (j < 4) ? (c0 + j) : (64 + c0 + j - 4);
                t1s[(r0 + i) * 129 + col] = v;
            }
    }
    __syncthreads();

    // GEMM2: feat = t1 @ mw2^T + b2, K = 128
    #pragma unroll
    for (int i = 0; i < 8; ++i)
        #pragma unroll
        for (int j = 0; j < 8; ++j) acc[i][j] = 0.f;
    #pragma unroll 8
    for (int k = 0; k < 128; ++k) {
        float a[8], b[8];
        #pragma unroll
        for (int i = 0; i < 8; ++i) a[i] = t1s[(r0 + i) * 129 + k];
        #pragma unroll
        for (int j = 0; j < 4; ++j) {
            b[j]     = w2s[(c0 + j) * 129 + k];
            b[4 + j] = w2s[(64 + c0 + j) * 129 + k];
        }
        #pragma unroll
        for (int i = 0; i < 8; ++i)
            #pragma unroll
            for (int j = 0; j < 8; ++j)
                acc[i][j] = fmaf(a[i], b[j], acc[i][j]);
    }
    float b2a[8];
    #pragma unroll
    for (int j = 0; j < 4; ++j) { b2a[j] = mb2[c0 + j]; b2a[4 + j] = mb2[64 + c0 + j]; }

    // ---- epilogue: segmented weighted accumulation (batch is sorted) ----
    int hA = cg >> 3;       // head of cols c0..c0+3    (0 or 1)
    int hB = 2 + hA;        // head of cols 64+c0..+3   (2 or 3)
    bool dd = ((cg & 7) == 0);  // designated denom accumulator for (hA,hB)
    int seg_base = sbat[0];

    float av[8];
    #pragma unroll
    for (int v = 0; v < 8; ++v) av[v] = 0.f;
    float dA = 0.f, dB = 0.f;
    int cur = -1;

    #pragma unroll
    for (int i = 0; i < 8; ++i) {
        int m = r0 + i;
        int s = sbat[m];
        if (s >= 0) {
            if (s != cur) {
                if (cur >= 0) {   // flush previous run
                    int loc = cur - seg_base;
                    if (loc < MAXLOC) {
                        #pragma unroll
                        for (int j = 0; j < 4; ++j) {
                            atomicAdd(&oac[loc * 128 + c0 + j],      av[j]);
                            atomicAdd(&oac[loc * 128 + 64 + c0 + j], av[4 + j]);
                        }
                        if (dd) { atomicAdd(&dac[loc * 4 + hA], dA);
                                  atomicAdd(&dac[loc * 4 + hB], dB); }
                    } else {
                        #pragma unroll
                        for (int j = 0; j < 4; ++j) {
                            atomicAdd(&out[(size_t)cur * 128 + c0 + j],      av[j]);
                            atomicAdd(&out[(size_t)cur * 128 + 64 + c0 + j], av[4 + j]);
                        }
                        if (dd) { atomicAdd(&g_denom[cur * 4 + hA], dA);
                                  atomicAdd(&g_denom[cur * 4 + hB], dB); }
                    }
                    #pragma unroll
                    for (int v = 0; v < 8; ++v) av[v] = 0.f;
                    dA = 0.f; dB = 0.f;
                }
                cur = s;
            }
            int node = m0 + m;
            float wA = expf(fminf(g_gate[(size_t)node * 4 + hA], 60.f));
            float wB = expf(fminf(g_gate[(size_t)node * 4 + hB], 60.f));
            #pragma unroll
            for (int j = 0; j < 4; ++j) {
                av[j]     = fmaf(wA, acc[i][j]     + b2a[j],     av[j]);
                av[4 + j] = fmaf(wB, acc[i][4 + j] + b2a[4 + j], av[4 + j]);
            }
            if (dd) { dA += wA; dB += wB; }
        }
    }
    if (cur >= 0) {   // final flush
        int loc = cur - seg_base;
        if (loc < MAXLOC) {
            #pragma unroll
            for (int j = 0; j < 4; ++j) {
                atomicAdd(&oac[loc * 128 + c0 + j],      av[j]);
                atomicAdd(&oac[loc * 128 + 64 + c0 + j], av[4 + j]);
            }
            if (dd) { atomicAdd(&dac[loc * 4 + hA], dA);
                      atomicAdd(&dac[loc * 4 + hB], dB); }
        } else {
            #pragma unroll
            for (int j = 0; j < 4; ++j) {
                atomicAdd(&out[(size_t)cur * 128 + c0 + j],      av[j]);
                atomicAdd(&out[(size_t)cur * 128 + 64 + c0 + j], av[4 + j]);
            }
            if (dd) { atomicAdd(&g_denom[cur * 4 + hA], dA);
                      atomicAdd(&g_denom[cur * 4 + hB], dB); }
        }
    }
    __syncthreads();

    // block-level flush of the smem segment accumulators
    int lastm = n - m0; if (lastm > 128) lastm = 128; lastm -= 1;
    int loc_cnt = sbat[lastm] - seg_base + 1;
    if (loc_cnt > MAXLOC) loc_cnt = MAXLOC;
    for (int idx = tid; idx < loc_cnt * 128; idx += 256) {
        int loc = idx >> 7, ch = idx & 127;
        atomicAdd(&out[(size_t)(seg_base + loc) * 128 + ch], oac[idx]);
    }
    if (tid < loc_cnt * 4)
        atomicAdd(&g_denom[(seg_base + (tid >> 2)) * 4 + (tid & 3)], dac[tid]);
}

// ------------------------------------------------------------------
// Pass C: divide by per-(segment,head) denominator
// ------------------------------------------------------------------
__global__ void k_div(float* __restrict__ out) {
    int i = blockIdx.x * blockDim.x + threadIdx.x;
    if (i < SEGS * MID) {
        int s = i >> 7, h = (i & 127) >> 5;
        out[i] = out[i] / (g_denom[s * 4 + h] + 1e-16f);
    }
}

// ------------------------------------------------------------------
extern "C" void kernel_launch(void* const* d_in, const int* in_sizes, int n_in,
                              void* d_out, int out_size)
{
    const float* x    = (const float*)d_in[0];
    const int*   bat  = (const int*)d_in[1];
    // d_in[2] = num_segments (unused, fixed 1024)
    const float* gw1  = (const float*)d_in[3];
    const float* pa   = (const float*)d_in[4];
    const float* gw2  = (const float*)d_in[5];
    const float* mw1  = (const float*)d_in[6];
    const float* mb1  = (const float*)d_in[7];
    const float* mw2  = (const float*)d_in[8];
    const float* mb2  = (const float*)d_in[9];
    float* out = (float*)d_out;
    int n = in_sizes[0] / IN_CH;

    const int a_smem = A_SMEM_FLOATS * 4;   // 87,296 B
    const int b_smem = B_SMEM_FLOATS * 4;   // 203,392 B
    cudaFuncSetAttribute(k_gate, cudaFuncAttributeMaxDynamicSharedMemorySize, a_smem);
    cudaFuncSetAttribute(k_feat, cudaFuncAttributeMaxDynamicSharedMemorySize, b_smem);

    k_init<<<(SEGS * MID + 255) / 256, 256>>>(out);
    k_gate<<<(n + 63) / 64, 256, a_smem>>>(x, gw1, gw2, pa, n);
    k_feat<<<(n + 127) / 128, 256, b_smem>>>(x, bat, mw1, mb1, mw2, mb2, out, n);
    k_div<<<(SEGS * MID + 255) / 256, 256>>>(out);
}

// round 13
// speedup vs baseline: 1.0024x; 1.0024x over previous
#include <cuda_runtime.h>
#include <math.h>

#define IN_CH   64
#define MID     128      // OUT_CH*HEADS
#define GH      256      // HEADS*IN_CH (gate hidden)
#define HEADS   4
#define SEGS    1024
#define MAXN    500000
#define MAXLOC  8

// scratch (static device globals — no runtime allocation)
__device__ float g_gate[(size_t)MAXN * HEADS];   // 8 MB
__device__ float g_denom[SEGS * HEADS];

// ------------------------------------------------------------------
// init: zero output accumulator and denominators
// ------------------------------------------------------------------
__global__ void k_init(float* __restrict__ out) {
    int i = blockIdx.x * blockDim.x + threadIdx.x;
    if (i < SEGS * MID)   out[i] = 0.f;
    if (i < SEGS * HEADS) g_denom[i] = 0.f;
}

// ------------------------------------------------------------------
// Pass A: gate[N,4] = prelu(x @ gw1^T) @ gw2^T
// block = 64 nodes, 256 threads, C tile [64 x 256] (8x8 micro per thread)
// smem: xs[64][65] | w1[256][65] | w2[4*256]
// ------------------------------------------------------------------
#define A_SMEM_FLOATS (64*65 + 256*65 + 1024)
__global__ __launch_bounds__(256) void k_gate(
    const float* __restrict__ x, const float* __restrict__ gw1,
    const float* __restrict__ gw2, const float* __restrict__ prelu_a, int n)
{
    extern __shared__ float sm[];
    float* xs  = sm;                    // 64*65 = 4160
    float* w1s = sm + 4160;             // 256*65 = 16640
    float* w2s = sm + 4160 + 16640;     // 1024

    int tid = threadIdx.x;
    int m0  = blockIdx.x * 64;

    {   // x tile (zero padded)
        const float4* x4 = (const float4*)x;
        #pragma unroll
        for (int t = 0; t < 4; ++t) {
            int fid = tid + t * 256;            // < 1024
            int m = fid >> 4, k4 = fid & 15;
            float4 v = make_float4(0.f, 0.f, 0.f, 0.f);
            if (m0 + m < n) v = x4[(size_t)(m0 + m) * 16 + k4];
            float* d = &xs[m * 65 + k4 * 4];
            d[0] = v.x; d[1] = v.y; d[2] = v.z; d[3] = v.w;
        }
        const float4* w14 = (const float4*)gw1;
        #pragma unroll
        for (int t = 0; t < 16; ++t) {
            int fid = tid + t * 256;            // < 4096
            int c = fid >> 4, k4 = fid & 15;
            float4 v = w14[fid];
            float* d = &w1s[c * 65 + k4 * 4];
            d[0] = v.x; d[1] = v.y; d[2] = v.z; d[3] = v.w;
        }
        ((float4*)w2s)[tid] = ((const float4*)gw2)[tid];  // 256 float4 = 1024 f
    }
    __syncthreads();

    int rg = tid >> 5, cg = tid & 31;   // warp = one row-group, lanes span cols
    int r0 = rg * 8, c0 = cg * 4;

    float acc[8][8];
    #pragma unroll
    for (int i = 0; i < 8; ++i)
        #pragma unroll
        for (int j = 0; j < 8; ++j) acc[i][j] = 0.f;

    #pragma unroll 8
    for (int k = 0; k < 64; ++k) {
        float a[8], b[8];
        #pragma unroll
        for (int i = 0; i < 8; ++i) a[i] = xs[(r0 + i) * 65 + k];
        #pragma unroll
        for (int j = 0; j < 4; ++j) {
            b[j]     = w1s[(c0 + j) * 65 + k];
            b[4 + j] = w1s[(128 + c0 + j) * 65 + k];
        }
        #pragma unroll
        for (int i = 0; i < 8; ++i)
            #pragma unroll
            for (int j = 0; j < 8; ++j)
                acc[i][j] = fmaf(a[i], b[j], acc[i][j]);
    }

    // PReLU + project onto 4 heads (per-lane partials over this lane's 8 cols)
    float slope = *prelu_a;
    float p[32];
    #pragma unroll
    for (int v = 0; v < 32; ++v) p[v] = 0.f;
    #pragma unroll
    for (int j = 0; j < 8; ++j) {
        int col = (j < 4) ? (c0 + j) : (128 + c0 + j - 4);
        float w0 = w2s[0 * 256 + col], w1v = w2s[1 * 256 + col];
        float w2v = w2s[2 * 256 + col], w3 = w2s[3 * 256 + col];
        #pragma unroll
        for (int i = 0; i < 8; ++i) {
            float h = acc[i][j];
            h = (h >= 0.f) ? h : slope * h;
            p[i * 4 + 0] = fmaf(h, w0,  p[i * 4 + 0]);
            p[i * 4 + 1] = fmaf(h, w1v, p[i * 4 + 1]);
            p[i * 4 + 2] = fmaf(h, w2v, p[i * 4 + 2]);
            p[i * 4 + 3] = fmaf(h, w3,  p[i * 4 + 3]);
        }
    }
    // warp allreduce of the 32 (node,head) partials
    #pragma unroll
    for (int s = 16; s > 0; s >>= 1)
        #pragma unroll
        for (int v = 0; v < 32; ++v)
            p[v] += __shfl_xor_sync(0xffffffffu, p[v], s);

    // lane l owns value l = i*4+h  (static select keeps p in registers)
    float myval = 0.f;
    #pragma unroll
    for (int v = 0; v < 32; ++v) myval = (v == cg) ? p[v] : myval;
    int i = cg >> 2, h = cg & 3;
    int node = m0 + r0 + i;
    if (node < n) g_gate[(size_t)node * 4 + h] = myval;
}

// ------------------------------------------------------------------
// Pass B: feat = relu(x@mw1^T + b1)@mw2^T + b2 ; w = exp(gate)
//         segmented accumulate  out += w*feat,  denom += w
// block = 128 nodes, 256 threads, C tile [128 x 128]
// ------------------------------------------------------------------
#define B_SMEM_FLOATS (128*65 + 128*65 + 128*129 + 128*129 + 8*128 + 32 + 128)
__global__ __launch_bounds__(256) void k_feat(
    const float* __restrict__ x, const int* __restrict__ batch,
    const float* __restrict__ mw1, const float* __restrict__ mb1,
    const float* __restrict__ mw2, const float* __restrict__ mb2,
    float* __restrict__ out, int n)
{
    extern __shared__ float sm[];
    float* xs  = sm;                    // 128*65  = 8320
    float* w1s = sm + 8320;             // 128*65  = 8320
    float* w2s = sm + 16640;            // 128*129 = 16512
    float* t1s = sm + 33152;            // 128*129 = 16512
    float* oac = sm + 49664;            // 8*128   = 1024
    float* dac = sm + 50688;            // 32
    int*  sbat = (int*)(sm + 50720);    // 128 ints

    int tid = threadIdx.x;
    int m0  = blockIdx.x * 128;

    {   // loads
        const float4* x4 = (const float4*)x;
        #pragma unroll
        for (int t = 0; t < 8; ++t) {
            int fid = tid + t * 256;            // < 2048
            int m = fid >> 4, k4 = fid & 15;
            float4 v = make_float4(0.f, 0.f, 0.f, 0.f);
            if (m0 + m < n) v = x4[(size_t)(m0 + m) * 16 + k4];
            float* d = &xs[m * 65 + k4 * 4];
            d[0] = v.x; d[1] = v.y; d[2] = v.z; d[3] = v.w;
        }
        const float4* w14 = (const float4*)mw1;
        #pragma unroll
        for (int t = 0; t < 8; ++t) {
            int fid = tid + t * 256;            // < 2048
            int c = fid >> 4, k4 = fid & 15;
            float4 v = w14[fid];
            float* d = &w1s[c * 65 + k4 * 4];
            d[0] = v.x; d[1] = v.y; d[2] = v.z; d[3] = v.w;
        }
        const float4* w24 = (const float4*)mw2;
        #pragma unroll
        for (int t = 0; t < 16; ++t) {
            int fid = tid + t * 256;            // < 4096
            int c = fid >> 5, k8 = fid & 31;
            float4 v = w24[fid];
            float* d = &w2s[c * 129 + k8 * 4];
            d[0] = v.x; d[1] = v.y; d[2] = v.z; d[3] = v.w;
        }
        if (tid < 128) sbat[tid] = (m0 + tid < n) ? batch[m0 + tid] : -1;
        for (int i = tid; i < 8 * 128; i += 256) oac[i] = 0.f;
        if (tid < 32) dac[tid] = 0.f;
    }
    __syncthreads();

    int rg = tid >> 4, cg = tid & 15;   // warp = 2 row-groups x 16 col-groups
    int r0 = rg * 8, c0 = cg * 4;

    float acc[8][8];
    #pragma unroll
    for (int i = 0; i < 8; ++i)
        #pragma unroll
        for (int j = 0; j < 8; ++j) acc[i][j] = 0.f;

    // GEMM1: t1 = relu(x @ mw1^T + b1), K = 64
    #pragma unroll 8
    for (int k = 0; k < 64; ++k) {
        float a[8], b[8];
        #pragma unroll
        for (int i = 0; i < 8; ++i) a[i] = xs[(r0 + i) * 65 + k];
        #pragma unroll
        for (int j = 0; j < 4; ++j) {
            b[j]     = w1s[(c0 + j) * 65 + k];
            b[4 + j] = w1s[(64 + c0 + j) * 65 + k];
        }
        #pragma unroll
        for (int i = 0; i < 8; ++i)
            #pragma unroll
            for (int j = 0; j < 8; ++j)
                acc[i][j] = fmaf(a[i], b[j], acc[i][j]);
    }
    {   // bias + relu -> t1s
        float b1a[8];
        #pragma unroll
        for (int j = 0; j < 4; ++j) { b1a[j] = mb1[c0 + j]; b1a[4 + j] = mb1[64 + c0 + j]; }
        #pragma unroll
        for (int i = 0; i < 8; ++i)
            #pragma unroll
            for (int j = 0; j < 8; ++j) {
                float v = acc[i][j] + b1a[j];
                v = fmaxf(v, 0.f);
                int col = (j < 4) ? (c0 + j) : (64 + c0 + j - 4);
                t1s[(r0 + i) * 129 + col] = v;
            }
    }
    __syncthreads();

    // GEMM2: feat = t1 @ mw2^T + b2, K = 128
    #pragma unroll
    for (int i = 0; i < 8; ++i)
        #pragma unroll
        for (int j = 0; j < 8; ++j) acc[i][j] = 0.f;
    #pragma unroll 8
    for (int k = 0; k < 128; ++k) {
        float a[8], b[8];
        #pragma unroll
        for (int i = 0; i < 8; ++i) a[i] = t1s[(r0 + i) * 129 + k];
        #pragma unroll
        for (int j = 0; j < 4; ++j) {
            b[j]     = w2s[(c0 + j) * 129 + k];
            b[4 + j] = w2s[(64 + c0 + j) * 129 + k];
        }
        #pragma unroll
        for (int i = 0; i < 8; ++i)
            #pragma unroll
            for (int j = 0; j < 8; ++j)
                acc[i][j] = fmaf(a[i], b[j], acc[i][j]);
    }
    float b2a[8];
    #pragma unroll
    for (int j = 0; j < 4; ++j) { b2a[j] = mb2[c0 + j]; b2a[4 + j] = mb2[64 + c0 + j]; }

    // ---- epilogue: segmented weighted accumulation (batch is sorted) ----
    int hA = cg >> 3;       // head of cols c0..c0+3    (0 or 1)
    int hB = 2 + hA;        // head of cols 64+c0..+3   (2 or 3)
    bool dd = ((cg & 7) == 0);  // designated denom accumulator for (hA,hB)
    int seg_base = sbat[0];

    float av[8];
    #pragma unroll
    for (int v = 0; v < 8; ++v) av[v] = 0.f;
    float dA = 0.f, dB = 0.f;
    int cur = -1;

    #pragma unroll
    for (int i = 0; i < 8; ++i) {
        int m = r0 + i;
        int s = sbat[m];
        if (s >= 0) {
            if (s != cur) {
                if (cur >= 0) {   // flush previous run
                    int loc = cur - seg_base;
                    if (loc < MAXLOC) {
                        #pragma unroll
                        for (int j = 0; j < 4; ++j) {
                            atomicAdd(&oac[loc * 128 + c0 + j],      av[j]);
                            atomicAdd(&oac[loc * 128 + 64 + c0 + j], av[4 + j]);
                        }
                        if (dd) { atomicAdd(&dac[loc * 4 + hA], dA);
                                  atomicAdd(&dac[loc * 4 + hB], dB); }
                    } else {
                        #pragma unroll
                        for (int j = 0; j < 4; ++j) {
                            atomicAdd(&out[(size_t)cur * 128 + c0 + j],      av[j]);
                            atomicAdd(&out[(size_t)cur * 128 + 64 + c0 + j], av[4 + j]);
                        }
                        if (dd) { atomicAdd(&g_denom[cur * 4 + hA], dA);
                                  atomicAdd(&g_denom[cur * 4 + hB], dB); }
                    }
                    #pragma unroll
                    for (int v = 0; v < 8; ++v) av[v] = 0.f;
                    dA = 0.f; dB = 0.f;
                }
                cur = s;
            }
            int node = m0 + m;
            float wA = expf(fminf(g_gate[(size_t)node * 4 + hA], 60.f));
            float wB = expf(fminf(g_gate[(size_t)node * 4 + hB], 60.f));
            #pragma unroll
            for (int j = 0; j < 4; ++j) {
                av[j]     = fmaf(wA, acc[i][j]     + b2a[j],     av[j]);
                av[4 + j] = fmaf(wB, acc[i][4 + j] + b2a[4 + j], av[4 + j]);
            }
            if (dd) { dA += wA; dB += wB; }
        }
    }
    if (cur >= 0) {   // final flush
        int loc = cur - seg_base;
        if (loc < MAXLOC) {
            #pragma unroll
            for (int j = 0; j < 4; ++j) {
                atomicAdd(&oac[loc * 128 + c0 + j],      av[j]);
                atomicAdd(&oac[loc * 128 + 64 + c0 + j], av[4 + j]);
            }
            if (dd) { atomicAdd(&dac[loc * 4 + hA], dA);
                      atomicAdd(&dac[loc * 4 + hB], dB); }
        } else {
            #pragma unroll
            for (int j = 0; j < 4; ++j) {
                atomicAdd(&out[(size_t)cur * 128 + c0 + j],      av[j]);
                atomicAdd(&out[(size_t)cur * 128 + 64 + c0 + j], av[4 + j]);
            }
            if (dd) { atomicAdd(&g_denom[cur * 4 + hA], dA);
                      atomicAdd(&g_denom[cur * 4 + hB], dB); }
        }
    }
    __syncthreads();

    // block-level flush of the smem segment accumulators
    int lastm = n - m0; if (lastm > 128) lastm = 128; lastm -= 1;
    int loc_cnt = sbat[lastm] - seg_base + 1;
    if (loc_cnt > MAXLOC) loc_cnt = MAXLOC;
    for (int idx = tid; idx < loc_cnt * 128; idx += 256) {
        int loc = idx >> 7, ch = idx & 127;
        atomicAdd(&out[(size_t)(seg_base + loc) * 128 + ch], oac[idx]);
    }
    if (tid < loc_cnt * 4)
        atomicAdd(&g_denom[(seg_base + (tid >> 2)) * 4 + (tid & 3)], dac[tid]);
}

// ------------------------------------------------------------------
// Pass C: divide by per-(segment,head) denominator
// ------------------------------------------------------------------
__global__ void k_div(float* __restrict__ out) {
    int i = blockIdx.x * blockDim.x + threadIdx.x;
    if (i < SEGS * MID) {
        int s = i >> 7, h = (i & 127) >> 5;
        out[i] = out[i] / (g_denom[s * 4 + h] + 1e-16f);
    }
}

// ------------------------------------------------------------------
extern "C" void kernel_launch(void* const* d_in, const int* in_sizes, int n_in,
                              void* d_out, int out_size)
{
    const float* x    = (const float*)d_in[0];
    const int*   bat  = (const int*)d_in[1];
    // d_in[2] = num_segments (unused, fixed 1024)
    const float* gw1  = (const float*)d_in[3];
    const float* pa   = (const float*)d_in[4];
    const float* gw2  = (const float*)d_in[5];
    const float* mw1  = (const float*)d_in[6];
    const float* mb1  = (const float*)d_in[7];
    const float* mw2  = (const float*)d_in[8];
    const float* mb2  = (const float*)d_in[9];
    float* out = (float*)d_out;
    int n = in_sizes[0] / IN_CH;

    const int a_smem = A_SMEM_FLOATS * 4;   // 87,296 B
    const int b_smem = B_SMEM_FLOATS * 4;   // 203,392 B
    cudaFuncSetAttribute(k_gate, cudaFuncAttributeMaxDynamicSharedMemorySize, a_smem);
    cudaFuncSetAttribute(k_feat, cudaFuncAttributeMaxDynamicSharedMemorySize, b_smem);

    k_init<<<(SEGS * MID + 255) / 256, 256>>>(out);
    k_gate<<<(n + 63) / 64, 256, a_smem>>>(x, gw1, gw2, pa, n);
    k_feat<<<(n + 127) / 128, 256, b_smem>>>(x, bat, mw1, mb1, mw2, mb2, out, n);
    k_div<<<(SEGS * MID + 255) / 256, 256>>>(out);
}

// round 14
// speedup vs baseline: 2.8563x; 2.8495x over previous
#include <cuda_runtime.h>
#include <math.h>

#define SEGS   1024
#define SX     68     // x smem row stride (words), 68 % 32 == 4 -> conflict-free frags
#define ST     132    // t1 smem row stride (words), 132 % 32 == 4

// scratch (static device globals — no runtime allocation)
__device__ float g_gate[(size_t)500000 * 4];   // stores exp(gate), clamped
__device__ float g_denom[SEGS * 4];

__device__ __forceinline__ unsigned f2tf(float f) {
    unsigned u; asm("cvt.rna.tf32.f32 %0, %1;" : "=r"(u) : "f"(f)); return u;
}

__device__ __forceinline__ void mma8(float c[4],
    unsigned a0, unsigned a1, unsigned a2, unsigned a3,
    unsigned b0, unsigned b1)
{
    asm volatile(
        "mma.sync.aligned.m16n8k8.row.col.f32.tf32.tf32.f32 "
        "{%0,%1,%2,%3},{%4,%5,%6,%7},{%8,%9},{%0,%1,%2,%3};"
        : "+f"(c[0]), "+f"(c[1]), "+f"(c[2]), "+f"(c[3])
        : "r"(a0), "r"(a1), "r"(a2), "r"(a3), "r"(b0), "r"(b1));
}

// pack W[outc][K] (row-major) into mma-B fragment layout (tf32 bits).
// word index: ((nt*(K/16)+ (k>>4))*32 + (n&7)*4 + (k&3))*4 + ((k>>3)&1)*2 + ((k>>2)&1)
// so one uint4 per (n_tile, ks-pair, lane): {b0,b1}@ks_even, {b0,b1}@ks_odd.
template<int K>
__device__ __forceinline__ void pack_b(unsigned* dst, const float4* src,
                                       int outc, int tid, int nthr)
{
    const int K4 = K / 4, KSP = K / 16;
    for (int idx = tid; idx < outc * K4; idx += nthr) {
        float4 v = src[idx];
        int nn = idx / K4, q = idx % K4;
        float vv[4] = {v.x, v.y, v.z, v.w};
        #pragma unroll
        for (int j = 0; j < 4; ++j) {
            int k = 4 * q + j;
            int w = (((nn >> 3) * KSP + (k >> 4)) * 32 + ((nn & 7) * 4 + (k & 3))) * 4
                    + ((k >> 3) & 1) * 2 + ((k >> 2) & 1);
            dst[w] = f2tf(vv[j]);
        }
    }
}

// ------------------------------------------------------------------
__global__ void k_init(float* __restrict__ out) {
    int i = blockIdx.x * blockDim.x + threadIdx.x;
    if (i < SEGS * 128) out[i] = 0.f;
    if (i < SEGS * 4)   g_denom[i] = 0.f;
}

// ------------------------------------------------------------------
// gate[N,4] = prelu(x @ gw1^T) @ gw2^T ; g_gate = exp(gate); denom += exp
// persistent; tile = 64 nodes; 8 warps (2m x 4n), warp tile 32x64
// ------------------------------------------------------------------
#define GATE_SMEM_W (16384 + 4352 + 1024 + 256 + 64)
__global__ __launch_bounds__(256, 2) void k_gate(
    const float* __restrict__ x, const int* __restrict__ batch,
    const float* __restrict__ gw1, const float* __restrict__ gw2,
    const float* __restrict__ prelu_a, int n, int ntiles)
{
    extern __shared__ unsigned smw[];
    unsigned* w1p   = smw;                       // 16384 : packed gw1 [256x64]
    unsigned* xs    = smw + 16384;               // 4352  : x tile tf32 [64][SX]
    float*    gw2s  = (float*)(smw + 20736);     // 1024  : gw2 fp32
    float*    sgate = (float*)(smw + 21760);     // 256   : gate acc [64][4]
    int*      sbat  = (int*)(smw + 22016);       // 64

    int tid = threadIdx.x;
    pack_b<64>(w1p, (const float4*)gw1, 256, tid, 256);
    for (int i = tid; i < 1024; i += 256) gw2s[i] = gw2[i];
    float slope = *prelu_a;

    int lane = tid & 31, g = lane >> 2, t = lane & 3;
    int wid = tid >> 5, wm = wid >> 2, wn = wid & 3;

    for (int tile = blockIdx.x; tile < ntiles; tile += gridDim.x) {
        int m0 = tile * 64;
        __syncthreads();
        {   // load x tile (tf32), zero sgate, load sbat
            const float4* x4 = (const float4*)x;
            #pragma unroll
            for (int i = 0; i < 4; ++i) {
                int fid = tid + i * 256, m = fid >> 4, q = fid & 15;
                float4 v = make_float4(0.f, 0.f, 0.f, 0.f);
                if (m0 + m < n) v = x4[(size_t)(m0 + m) * 16 + q];
                uint4 u; u.x = f2tf(v.x); u.y = f2tf(v.y); u.z = f2tf(v.z); u.w = f2tf(v.w);
                *(uint4*)(xs + m * SX + 4 * q) = u;
            }
            sgate[tid] = 0.f;
            if (tid < 64) sbat[tid] = batch[min(m0 + tid, n - 1)];
        }
        __syncthreads();

        float acc[2][8][4];
        #pragma unroll
        for (int a = 0; a < 2; ++a)
            #pragma unroll
            for (int b = 0; b < 8; ++b)
                #pragma unroll
                for (int c = 0; c < 4; ++c) acc[a][b][c] = 0.f;

        #pragma unroll
        for (int ksp = 0; ksp < 4; ++ksp) {
            unsigned a[2][2][4];
            #pragma unroll
            for (int mt = 0; mt < 2; ++mt)
                #pragma unroll
                for (int sub = 0; sub < 2; ++sub) {
                    const unsigned* p = xs + (wm * 32 + mt * 16 + g) * SX + (2 * ksp + sub) * 8 + t;
                    a[mt][sub][0] = p[0];
                    a[mt][sub][1] = p[8 * SX];
                    a[mt][sub][2] = p[4];
                    a[mt][sub][3] = p[8 * SX + 4];
                }
            #pragma unroll
            for (int half = 0; half < 2; ++half) {
                uint4 bq[4];
                #pragma unroll
                for (int j = 0; j < 4; ++j)
                    bq[j] = *(const uint4*)(w1p + (((wn * 8 + half * 4 + j) * 4 + ksp) * 32 + lane) * 4);
                #pragma unroll
                for (int j = 0; j < 4; ++j)
                    #pragma unroll
                    for (int mt = 0; mt < 2; ++mt) {
                        mma8(acc[mt][half * 4 + j], a[mt][0][0], a[mt][0][1], a[mt][0][2], a[mt][0][3], bq[j].x, bq[j].y);
                        mma8(acc[mt][half * 4 + j], a[mt][1][0], a[mt][1][1], a[mt][1][2], a[mt][1][3], bq[j].z, bq[j].w);
                    }
            }
        }

        // prelu + project onto 4 heads (fp32 scalar)
        float part[2][2][4];
        #pragma unroll
        for (int a = 0; a < 2; ++a)
            #pragma unroll
            for (int b = 0; b < 2; ++b)
                #pragma unroll
                for (int c = 0; c < 4; ++c) part[a][b][c] = 0.f;

        #pragma unroll
        for (int nt = 0; nt < 8; ++nt)
            #pragma unroll
            for (int e = 0; e < 2; ++e) {
                int col = wn * 64 + nt * 8 + 2 * t + e;
                float w0 = gw2s[col], w1v = gw2s[256 + col];
                float w2v = gw2s[512 + col], w3 = gw2s[768 + col];
                #pragma unroll
                for (int mt = 0; mt < 2; ++mt)
                    #pragma unroll
                    for (int i = 0; i < 2; ++i) {
                        float h = acc[mt][nt][i * 2 + e];
                        h = (h >= 0.f) ? h : slope * h;
                        part[mt][i][0] = fmaf(h, w0,  part[mt][i][0]);
                        part[mt][i][1] = fmaf(h, w1v, part[mt][i][1]);
                        part[mt][i][2] = fmaf(h, w2v, part[mt][i][2]);
                        part[mt][i][3] = fmaf(h, w3,  part[mt][i][3]);
                    }
            }
        // reduce over t lanes (xor 1,2)
        #pragma unroll
        for (int off = 1; off <= 2; off <<= 1)
            #pragma unroll
            for (int mt = 0; mt < 2; ++mt)
                #pragma unroll
                for (int i = 0; i < 2; ++i)
                    #pragma unroll
                    for (int h = 0; h < 4; ++h)
                        part[mt][i][h] += __shfl_xor_sync(0xffffffffu, part[mt][i][h], off);
        if (t == 0) {
            #pragma unroll
            for (int mt = 0; mt < 2; ++mt)
                #pragma unroll
                for (int i = 0; i < 2; ++i) {
                    int r = wm * 32 + mt * 16 + g + 8 * i;
                    #pragma unroll
                    for (int h = 0; h < 4; ++h)
                        atomicAdd(&sgate[r * 4 + h], part[mt][i][h]);
                }
        }
        __syncthreads();

        {   // epilogue: exp + store + denom
            int m = tid >> 2, h = tid & 3;
            int node = m0 + m;
            if (node < n) {
                float w = expf(fminf(sgate[tid], 60.f));
                g_gate[(size_t)node * 4 + h] = w;
                atomicAdd(&g_denom[sbat[m] * 4 + h], w);
            }
        }
    }
}

// ------------------------------------------------------------------
// feat = relu(x@mw1^T+b1)@(mw2hi+mw2lo)^T ; out[seg] += exp_gate * feat
// persistent; tile = 64 nodes; 8 warps (2m x 4n), warp tile 32x32; head = wn
// ------------------------------------------------------------------
#define FEAT_SMEM_W (8192 + 16384 + 16384 + 4352 + 8448 + 128 + 256 + 64)
__global__ __launch_bounds__(256, 1) void k_feat(
    const float* __restrict__ x, const int* __restrict__ batch,
    const float* __restrict__ mw1, const float* __restrict__ mb1,
    const float* __restrict__ mw2, float* __restrict__ out, int n, int ntiles)
{
    extern __shared__ unsigned smw[];
    unsigned* w1p = smw;                      // 8192  : packed mw1 [128x64]
    unsigned* w2h = smw + 8192;               // 16384 : packed mw2 hi
    unsigned* w2l = smw + 24576;              // 16384 : packed mw2 lo
    unsigned* xs  = smw + 40960;              // 4352  : x tile tf32
    unsigned* t1s = smw + 45312;              // 8448  : t1 tile tf32 [64][ST]
    float*    sb1 = (float*)(smw + 53760);    // 128
    float*    sew = (float*)(smw + 53888);    // 256   : exp(gate) [64][4]
    int*      sbat= (int*)(smw + 54144);      // 64

    int tid = threadIdx.x;
    pack_b<64>(w1p, (const float4*)mw1, 128, tid, 256);
    {   // split-pack mw2: hi = tf32(w), lo = tf32(w - hi)
        const float4* src = (const float4*)mw2;
        for (int idx = tid; idx < 128 * 32; idx += 256) {
            float4 v = src[idx];
            int nn = idx >> 5, q = idx & 31;
            float vv[4] = {v.x, v.y, v.z, v.w};
            #pragma unroll
            for (int j = 0; j < 4; ++j) {
                int k = 4 * q + j;
                int w = (((nn >> 3) * 8 + (k >> 4)) * 32 + ((nn & 7) * 4 + (k & 3))) * 4
                        + ((k >> 3) & 1) * 2 + ((k >> 2) & 1);
                unsigned hi = f2tf(vv[j]);
                w2h[w] = hi;
                w2l[w] = f2tf(vv[j] - __uint_as_float(hi));
            }
        }
    }
    for (int i = tid; i < 128; i += 256) sb1[i] = mb1[i];

    int lane = tid & 31, g = lane >> 2, t = lane & 3;
    int wid = tid >> 5, wm = wid >> 2, wn = wid & 3;

    for (int tile = blockIdx.x; tile < ntiles; tile += gridDim.x) {
        int m0 = tile * 64;
        __syncthreads();
        {   // loads
            const float4* x4 = (const float4*)x;
            #pragma unroll
            for (int i = 0; i < 4; ++i) {
                int fid = tid + i * 256, m = fid >> 4, q = fid & 15;
                float4 v = make_float4(0.f, 0.f, 0.f, 0.f);
                if (m0 + m < n) v = x4[(size_t)(m0 + m) * 16 + q];
                uint4 u; u.x = f2tf(v.x); u.y = f2tf(v.y); u.z = f2tf(v.z); u.w = f2tf(v.w);
                *(uint4*)(xs + m * SX + 4 * q) = u;
            }
            int m = tid >> 2, h = tid & 3;
            sew[tid] = (m0 + m < n) ? g_gate[(size_t)(m0 + m) * 4 + h] : 0.f;
            if (tid < 64) sbat[tid] = batch[min(m0 + tid, n - 1)];
        }
        __syncthreads();

        // GEMM1: t1 = relu(x @ mw1^T + b1), K=64
        float acc1[2][4][4];
        #pragma unroll
        for (int a = 0; a < 2; ++a)
            #pragma unroll
            for (int b = 0; b < 4; ++b)
                #pragma unroll
                for (int c = 0; c < 4; ++c) acc1[a][b][c] = 0.f;

        #pragma unroll
        for (int ksp = 0; ksp < 4; ++ksp) {
            unsigned a[2][2][4];
            #pragma unroll
            for (int mt = 0; mt < 2; ++mt)
                #pragma unroll
                for (int sub = 0; sub < 2; ++sub) {
                    const unsigned* p = xs + (wm * 32 + mt * 16 + g) * SX + (2 * ksp + sub) * 8 + t;
                    a[mt][sub][0] = p[0];
                    a[mt][sub][1] = p[8 * SX];
                    a[mt][sub][2] = p[4];
                    a[mt][sub][3] = p[8 * SX + 4];
                }
            #pragma unroll
            for (int j = 0; j < 4; ++j) {
                uint4 b = *(const uint4*)(w1p + (((wn * 4 + j) * 4 + ksp) * 32 + lane) * 4);
                #pragma unroll
                for (int mt = 0; mt < 2; ++mt) {
                    mma8(acc1[mt][j], a[mt][0][0], a[mt][0][1], a[mt][0][2], a[mt][0][3], b.x, b.y);
                    mma8(acc1[mt][j], a[mt][1][0], a[mt][1][1], a[mt][1][2], a[mt][1][3], b.z, b.w);
                }
            }
        }
        // bias + relu + store t1 as tf32
        #pragma unroll
        for (int nt = 0; nt < 4; ++nt) {
            int c0 = wn * 32 + nt * 8 + 2 * t;
            float bb0 = sb1[c0], bb1 = sb1[c0 + 1];
            #pragma unroll
            for (int mt = 0; mt < 2; ++mt) {
                int r = wm * 32 + mt * 16 + g;
                t1s[r * ST + c0]           = f2tf(fmaxf(acc1[mt][nt][0] + bb0, 0.f));
                t1s[r * ST + c0 + 1]       = f2tf(fmaxf(acc1[mt][nt][1] + bb1, 0.f));
                t1s[(r + 8) * ST + c0]     = f2tf(fmaxf(acc1[mt][nt][2] + bb0, 0.f));
                t1s[(r + 8) * ST + c0 + 1] = f2tf(fmaxf(acc1[mt][nt][3] + bb1, 0.f));
            }
        }
        __syncthreads();

        // GEMM2: feat = t1 @ mw2^T (split hi+lo), K=128
        float acc2[2][4][4];
        #pragma unroll
        for (int a = 0; a < 2; ++a)
            #pragma unroll
            for (int b = 0; b < 4; ++b)
                #pragma unroll
                for (int c = 0; c < 4; ++c) acc2[a][b][c] = 0.f;

        #pragma unroll
        for (int ksp = 0; ksp < 8; ++ksp) {
            unsigned a[2][2][4];
            #pragma unroll
            for (int mt = 0; mt < 2; ++mt)
                #pragma unroll
                for (int sub = 0; sub < 2; ++sub) {
                    const unsigned* p = t1s + (wm * 32 + mt * 16 + g) * ST + (2 * ksp + sub) * 8 + t;
                    a[mt][sub][0] = p[0];
                    a[mt][sub][1] = p[8 * ST];
                    a[mt][sub][2] = p[4];
                    a[mt][sub][3] = p[8 * ST + 4];
                }
            #pragma unroll
            for (int j = 0; j < 4; ++j) {
                int bidx = (((wn * 4 + j) * 8 + ksp) * 32 + lane) * 4;
                uint4 bh = *(const uint4*)(w2h + bidx);
                uint4 bl = *(const uint4*)(w2l + bidx);
                #pragma unroll
                for (int mt = 0; mt < 2; ++mt) {
                    mma8(acc2[mt][j], a[mt][0][0], a[mt][0][1], a[mt][0][2], a[mt][0][3], bh.x, bh.y);
                    mma8(acc2[mt][j], a[mt][0][0], a[mt][0][1], a[mt][0][2], a[mt][0][3], bl.x, bl.y);
                    mma8(acc2[mt][j], a[mt][1][0], a[mt][1][1], a[mt][1][2], a[mt][1][3], bh.z, bh.w);
                    mma8(acc2[mt][j], a[mt][1][0], a[mt][1][1], a[mt][1][2], a[mt][1][3], bl.z, bl.w);
                }
            }
        }

        // ---- segmented weighted pooling epilogue (batch sorted) ----
        float wv[2][2]; int sg[2][2];
        #pragma unroll
        for (int mt = 0; mt < 2; ++mt)
            #pragma unroll
            for (int i = 0; i < 2; ++i) {
                int r = wm * 32 + mt * 16 + g + 8 * i;
                wv[mt][i] = sew[r * 4 + wn];
                sg[mt][i] = sbat[r];
            }
        int s0 = sbat[wm * 32], s1 = sbat[wm * 32 + 31];
        for (int s = s0; s <= s1; ++s) {
            float p[8];
            #pragma unroll
            for (int v = 0; v < 8; ++v) p[v] = 0.f;
            #pragma unroll
            for (int mt = 0; mt < 2; ++mt)
                #pragma unroll
                for (int i = 0; i < 2; ++i)
                    if (sg[mt][i] == s) {
                        float w = wv[mt][i];
                        #pragma unroll
                        for (int nt = 0; nt < 4; ++nt) {
                            p[nt * 2]     = fmaf(w, acc2[mt][nt][i * 2],     p[nt * 2]);
                            p[nt * 2 + 1] = fmaf(w, acc2[mt][nt][i * 2 + 1], p[nt * 2 + 1]);
                        }
                    }
            #pragma unroll
            for (int off = 4; off <= 16; off <<= 1)
                #pragma unroll
                for (int v = 0; v < 8; ++v)
                    p[v] += __shfl_xor_sync(0xffffffffu, p[v], off);
            if (g == 0) {
                #pragma unroll
                for (int nt = 0; nt < 4; ++nt) {
                    atomicAdd(&out[(size_t)s * 128 + wn * 32 + nt * 8 + 2 * t],     p[nt * 2]);
                    atomicAdd(&out[(size_t)s * 128 + wn * 32 + nt * 8 + 2 * t + 1], p[nt * 2 + 1]);
                }
            }
        }
    }
}

// ------------------------------------------------------------------
// out = (pool + b2*D) / (D + 1e-16)
// ------------------------------------------------------------------
__global__ void k_div(float* __restrict__ out, const float* __restrict__ b2) {
    int i = blockIdx.x * blockDim.x + threadIdx.x;
    if (i < SEGS * 128) {
        int c = i & 127;
        float D = g_denom[(i >> 7) * 4 + (c >> 5)];
        out[i] = (out[i] + b2[c] * D) / (D + 1e-16f);
    }
}

// ------------------------------------------------------------------
extern "C" void kernel_launch(void* const* d_in, const int* in_sizes, int n_in,
                              void* d_out, int out_size)
{
    const float* x   = (const float*)d_in[0];
    const int*   bat = (const int*)d_in[1];
    // d_in[2] = num_segments (fixed 1024)
    const float* gw1 = (const float*)d_in[3];
    const float* pa  = (const float*)d_in[4];
    const float* gw2 = (const float*)d_in[5];
    const float* mw1 = (const float*)d_in[6];
    const float* mb1 = (const float*)d_in[7];
    const float* mw2 = (const float*)d_in[8];
    const float* mb2 = (const float*)d_in[9];
    float* out = (float*)d_out;

    int n = in_sizes[0] / 64;
    int ntiles = (n + 63) / 64;
    int sms = 148;
    cudaDeviceGetAttribute(&sms, cudaDevAttrMultiProcessorCount, 0);

    const int gate_smem = GATE_SMEM_W * 4;   // 88,320 B  (2 CTA/SM)
    const int feat_smem = FEAT_SMEM_W * 4;   // 216,832 B (1 CTA/SM)
    cudaFuncSetAttribute(k_gate, cudaFuncAttributeMaxDynamicSharedMemorySize, gate_smem);
    cudaFuncSetAttribute(k_feat, cudaFuncAttributeMaxDynamicSharedMemorySize, feat_smem);

    k_init<<<(SEGS * 128 + 255) / 256, 256>>>(out);
    k_gate<<<2 * sms, 256, gate_smem>>>(x, bat, gw1, gw2, pa, n, ntiles);
    k_feat<<<sms, 256, feat_smem>>>(x, bat, mw1, mb1, mw2, out, n, ntiles);
    k_div<<<(SEGS * 128 + 255) / 256, 256>>>(out, mb2);
}

// round 15
// speedup vs baseline: 4.7942x; 1.6784x over previous
#include <cuda_runtime.h>
#include <cuda_bf16.h>
#include <math.h>

#define SEGS 1024

// scratch (static device globals — no runtime allocation)
__device__ float g_gate[(size_t)500000 * 4];   // exp(gate)
__device__ float g_denom[SEGS * 4];

// pack two fp32 -> bf16x2 (lo -> low half, hi -> high half)
__device__ __forceinline__ unsigned packbf(float lo, float hi) {
    unsigned r;
    asm("cvt.rn.bf16x2.f32 %0, %1, %2;" : "=r"(r) : "f"(hi), "f"(lo));
    return r;
}

__device__ __forceinline__ void mma16(float c[4],
    unsigned a0, unsigned a1, unsigned a2, unsigned a3,
    unsigned b0, unsigned b1)
{
    asm volatile(
        "mma.sync.aligned.m16n8k16.row.col.f32.bf16.bf16.f32 "
        "{%0,%1,%2,%3},{%4,%5,%6,%7},{%8,%9},{%0,%1,%2,%3};"
        : "+f"(c[0]), "+f"(c[1]), "+f"(c[2]), "+f"(c[3])
        : "r"(a0), "r"(a1), "r"(a2), "r"(a3), "r"(b0), "r"(b1));
}

// pack W[outc][K] row-major -> bf16 B-fragment layout.
// uint2 per (nt, kc, lane): b0 = {W[n0+g][k0+2t], +1}, b1 = {W[n0+g][k0+2t+8], +9}
template<int K>
__device__ __forceinline__ void pack_b_bf(__nv_bfloat16* dst, const float4* src,
                                          int outc, int tid)
{
    const int K4 = K / 4, KCH = K / 16;
    for (int idx = tid; idx < outc * K4; idx += 256) {
        float4 v = src[idx];
        int n = idx / K4, q = idx % K4;
        int g = n & 7, nt = n >> 3;
        float vv[4] = {v.x, v.y, v.z, v.w};
        #pragma unroll
        for (int j = 0; j < 4; ++j) {
            int k = 4 * q + j;
            int kc = k >> 4, r = k & 15;
            int word = (((nt * KCH + kc) * 32) + g * 4 + ((r & 7) >> 1)) * 2 + (r >> 3);
            dst[word * 2 + (k & 1)] = __float2bfloat16(vv[j]);
        }
    }
}

// ------------------------------------------------------------------
__global__ void k_init(float* __restrict__ out) {
    int i = blockIdx.x * blockDim.x + threadIdx.x;
    if (i < SEGS * 128) out[i] = 0.f;
    if (i < SEGS * 4)   g_denom[i] = 0.f;
}

// ------------------------------------------------------------------
// k_gate: g_gate = exp(prelu(x@gw1^T)@gw2^T); denom += exp
// persistent, tile = 64 nodes, 8 warps (2m x 4n), warp tile 32x64
// projection onto 4 heads done with MMA (C-frag -> A-frag reuse)
// ------------------------------------------------------------------
// smem words: w1p 8192 | gw2p 1024 | xs 64*36=2304 | sgp 4*64*8=2048 | sbat 64
#define GATE_SMEM_W (8192 + 1024 + 2304 + 2048 + 64)
__global__ __launch_bounds__(256, 2) void k_gate(
    const float* __restrict__ x, const int* __restrict__ batch,
    const float* __restrict__ gw1, const float* __restrict__ gw2,
    const float* __restrict__ prelu_a, int n, int ntiles)
{
    extern __shared__ unsigned smw[];
    unsigned* w1p  = smw;                       // packed gw1 [256x64]
    unsigned* gw2p = smw + 8192;                // packed gw2 [8(pad)x256]
    unsigned* xs   = smw + 9216;                // x tile bf16 [64][36w]
    float*    sgp  = (float*)(smw + 11520);     // partial gate [4wn][64][8]
    int*      sbat = (int*)(smw + 13568);       // 64

    int tid = threadIdx.x;
    // weight packing (once per CTA)
    pack_b_bf<64>((__nv_bfloat16*)w1p, (const float4*)gw1, 256, tid);
    for (int i = tid; i < 1024; i += 256) gw2p[i] = 0;
    __syncthreads();
    {   // gw2 [4][256] -> B frags (heads 4..7 zero)
        const float4* g4 = (const float4*)gw2;
        __nv_bfloat16* dh = (__nv_bfloat16*)gw2p;
        if (tid < 256) {
            float4 v = g4[tid];
            int nn = tid >> 6, q = tid & 63;
            float vv[4] = {v.x, v.y, v.z, v.w};
            #pragma unroll
            for (int j = 0; j < 4; ++j) {
                int k = 4 * q + j;
                int kc = k >> 4, r = k & 15;
                int word = ((kc * 32) + nn * 4 + ((r & 7) >> 1)) * 2 + (r >> 3);
                dh[word * 2 + (k & 1)] = __float2bfloat16(vv[j]);
            }
        }
    }
    float slope = *prelu_a;

    int lane = tid & 31, g = lane >> 2, t = lane & 3;
    int wid = tid >> 5, wm = wid >> 2, wn = wid & 3;
    const uint2* w1u = (const uint2*)w1p;
    const uint2* g2u = (const uint2*)gw2p;

    for (int tile = blockIdx.x; tile < ntiles; tile += gridDim.x) {
        int m0 = tile * 64;
        __syncthreads();
        {   // x tile -> bf16
            const float4* x4 = (const float4*)x;
            #pragma unroll
            for (int i = 0; i < 4; ++i) {
                int fid = tid + i * 256, m = fid >> 4, q = fid & 15;
                float4 v = make_float4(0.f, 0.f, 0.f, 0.f);
                if (m0 + m < n) v = x4[(size_t)(m0 + m) * 16 + q];
                uint2 u; u.x = packbf(v.x, v.y); u.y = packbf(v.z, v.w);
                *(uint2*)(xs + m * 36 + q * 2) = u;
            }
            if (tid < 64) sbat[tid] = (m0 + tid < n) ? batch[m0 + tid] : batch[n - 1];
        }
        __syncthreads();

        float acc[2][8][4];
        #pragma unroll
        for (int a = 0; a < 2; ++a)
            #pragma unroll
            for (int b = 0; b < 8; ++b)
                #pragma unroll
                for (int c = 0; c < 4; ++c) acc[a][b][c] = 0.f;

        #pragma unroll
        for (int kc = 0; kc < 4; ++kc) {
            unsigned a[2][4];
            #pragma unroll
            for (int mt = 0; mt < 2; ++mt) {
                const unsigned* p = xs + (wm * 32 + mt * 16 + g) * 36 + kc * 8 + t;
                a[mt][0] = p[0]; a[mt][1] = p[288]; a[mt][2] = p[4]; a[mt][3] = p[292];
            }
            #pragma unroll
            for (int nt = 0; nt < 8; ++nt) {
                uint2 b = w1u[((wn * 8 + nt) * 4 + kc) * 32 + lane];
                #pragma unroll
                for (int mt = 0; mt < 2; ++mt)
                    mma16(acc[mt][nt], a[mt][0], a[mt][1], a[mt][2], a[mt][3], b.x, b.y);
            }
        }

        // PReLU + head projection via MMA (C frags become A frags)
        #pragma unroll
        for (int mt = 0; mt < 2; ++mt) {
            float pacc[4] = {0.f, 0.f, 0.f, 0.f};
            #pragma unroll
            for (int kcl = 0; kcl < 4; ++kcl) {
                int ne = 2 * kcl, no = ne + 1;
                float h[8];
                #pragma unroll
                for (int e = 0; e < 4; ++e) { h[e] = acc[mt][ne][e]; h[4 + e] = acc[mt][no][e]; }
                #pragma unroll
                for (int e = 0; e < 8; ++e) h[e] = fmaxf(h[e], 0.f) + slope * fminf(h[e], 0.f);
                unsigned a0 = packbf(h[0], h[1]), a1 = packbf(h[2], h[3]);
                unsigned a2 = packbf(h[4], h[5]), a3 = packbf(h[6], h[7]);
                uint2 b = g2u[(wn * 4 + kcl) * 32 + lane];
                mma16(pacc, a0, a1, a2, a3, b.x, b.y);
            }
            int row = wm * 32 + mt * 16 + g;
            *(float2*)&sgp[wn * 512 + row * 8 + 2 * t]       = make_float2(pacc[0], pacc[1]);
            *(float2*)&sgp[wn * 512 + (row + 8) * 8 + 2 * t] = make_float2(pacc[2], pacc[3]);
        }
        __syncthreads();

        {   // reduce over wn, exp, store, denom
            int row = tid >> 2, h = tid & 3;
            if (m0 + row < n) {
                float gs = sgp[row * 8 + h] + sgp[512 + row * 8 + h]
                         + sgp[1024 + row * 8 + h] + sgp[1536 + row * 8 + h];
                float w = expf(fminf(gs, 60.f));
                g_gate[(size_t)(m0 + row) * 4 + h] = w;
                atomicAdd(&g_denom[sbat[row] * 4 + h], w);
            }
        }
    }
}

// ------------------------------------------------------------------
// k_feat: feat = relu(x@mw1^T+b1)@(mw2hi+mw2lo)^T ; out[seg] += w*feat
// persistent, tile = 128 nodes, 8 warps (2m x 4n), warp tile 64x32
// ------------------------------------------------------------------
// words: w1p 4096 | w2h 8192 | w2l 8192 | xs 128*36=4608 | t1s 128*68=8704
//        sb1 128 | sew 512 | sbat 128
#define FEAT_SMEM_W (4096 + 8192 + 8192 + 4608 + 8704 + 128 + 512 + 128)
__global__ __launch_bounds__(256, 1) void k_feat(
    const float* __restrict__ x, const int* __restrict__ batch,
    const float* __restrict__ mw1, const float* __restrict__ mb1,
    const float* __restrict__ mw2, float* __restrict__ out, int n, int ntiles)
{
    extern __shared__ unsigned smw[];
    unsigned* w1p = smw;                      // packed mw1 [128x64]
    unsigned* w2h = smw + 4096;               // packed mw2 hi
    unsigned* w2l = smw + 12288;              // packed mw2 lo
    unsigned* xs  = smw + 20480;              // x tile bf16 [128][36w]
    unsigned* t1s = smw + 25088;              // t1 bf16 [128][68w]
    float*    sb1 = (float*)(smw + 33792);    // 128
    float*    sew = (float*)(smw + 33920);    // 512: exp(gate) [128][4]
    int*      sbat= (int*)(smw + 34432);      // 128

    int tid = threadIdx.x;
    pack_b_bf<64>((__nv_bfloat16*)w1p, (const float4*)mw1, 128, tid);
    {   // split-pack mw2: hi = bf16(w), lo = bf16(w - hi)
        const float4* src = (const float4*)mw2;
        __nv_bfloat16* dh = (__nv_bfloat16*)w2h;
        __nv_bfloat16* dl = (__nv_bfloat16*)w2l;
        for (int idx = tid; idx < 128 * 32; idx += 256) {
            float4 v = src[idx];
            int nn = idx >> 5, q = idx & 31;
            int g = nn & 7, nt = nn >> 3;
            float vv[4] = {v.x, v.y, v.z, v.w};
            #pragma unroll
            for (int j = 0; j < 4; ++j) {
                int k = 4 * q + j;
                int kc = k >> 4, r = k & 15;
                int hw = ((((nt * 8 + kc) * 32) + g * 4 + ((r & 7) >> 1)) * 2 + (r >> 3)) * 2 + (k & 1);
                __nv_bfloat16 hi = __float2bfloat16(vv[j]);
                dh[hw] = hi;
                dl[hw] = __float2bfloat16(vv[j] - __bfloat162float(hi));
            }
        }
    }
    for (int i = tid; i < 128; i += 256) sb1[i] = mb1[i];

    int lane = tid & 31, g = lane >> 2, t = lane & 3;
    int wid = tid >> 5, wm = wid >> 2, wn = wid & 3;
    const uint2* w1u = (const uint2*)w1p;
    const uint2* whu = (const uint2*)w2h;
    const uint2* wlu = (const uint2*)w2l;

    for (int tile = blockIdx.x; tile < ntiles; tile += gridDim.x) {
        int m0 = tile * 128;
        __syncthreads();
        {   // loads
            const float4* x4 = (const float4*)x;
            #pragma unroll
            for (int i = 0; i < 8; ++i) {
                int fid = tid + i * 256, m = fid >> 4, q = fid & 15;
                float4 v = make_float4(0.f, 0.f, 0.f, 0.f);
                if (m0 + m < n) v = x4[(size_t)(m0 + m) * 16 + q];
                uint2 u; u.x = packbf(v.x, v.y); u.y = packbf(v.z, v.w);
                *(uint2*)(xs + m * 36 + q * 2) = u;
            }
            #pragma unroll
            for (int i = 0; i < 2; ++i) {
                int e = tid + i * 256, m = e >> 2, h = e & 3;
                sew[e] = (m0 + m < n) ? g_gate[(size_t)(m0 + m) * 4 + h] : 0.f;
            }
            if (tid < 128) sbat[tid] = (m0 + tid < n) ? batch[m0 + tid] : batch[n - 1];
        }
        __syncthreads();

        // GEMM1: t1 = relu(x @ mw1^T + b1), K=64
        float acc1[4][4][4];
        #pragma unroll
        for (int a = 0; a < 4; ++a)
            #pragma unroll
            for (int b = 0; b < 4; ++b)
                #pragma unroll
                for (int c = 0; c < 4; ++c) acc1[a][b][c] = 0.f;

        #pragma unroll
        for (int kc = 0; kc < 4; ++kc) {
            unsigned a[4][4];
            #pragma unroll
            for (int mt = 0; mt < 4; ++mt) {
                const unsigned* p = xs + (wm * 64 + mt * 16 + g) * 36 + kc * 8 + t;
                a[mt][0] = p[0]; a[mt][1] = p[288]; a[mt][2] = p[4]; a[mt][3] = p[292];
            }
            #pragma unroll
            for (int nt = 0; nt < 4; ++nt) {
                uint2 b = w1u[((wn * 4 + nt) * 4 + kc) * 32 + lane];
                #pragma unroll
                for (int mt = 0; mt < 4; ++mt)
                    mma16(acc1[mt][nt], a[mt][0], a[mt][1], a[mt][2], a[mt][3], b.x, b.y);
            }
        }
        // bias + relu -> t1s (bf16 pairs, conflict-free)
        #pragma unroll
        for (int nt = 0; nt < 4; ++nt) {
            int c0 = wn * 32 + nt * 8 + 2 * t;
            float b0v = sb1[c0], b1v = sb1[c0 + 1];
            int cw = wn * 16 + nt * 4 + t;
            #pragma unroll
            for (int mt = 0; mt < 4; ++mt) {
                int row = wm * 64 + mt * 16 + g;
                t1s[row * 68 + cw] = packbf(fmaxf(acc1[mt][nt][0] + b0v, 0.f),
                                            fmaxf(acc1[mt][nt][1] + b1v, 0.f));
                t1s[(row + 8) * 68 + cw] = packbf(fmaxf(acc1[mt][nt][2] + b0v, 0.f),
                                                  fmaxf(acc1[mt][nt][3] + b1v, 0.f));
            }
        }
        __syncthreads();

        // GEMM2: feat = t1 @ mw2^T (split hi+lo), K=128
        float acc2[4][4][4];
        #pragma unroll
        for (int a = 0; a < 4; ++a)
            #pragma unroll
            for (int b = 0; b < 4; ++b)
                #pragma unroll
                for (int c = 0; c < 4; ++c) acc2[a][b][c] = 0.f;

        #pragma unroll
        for (int kc = 0; kc < 8; ++kc) {
            unsigned a[4][4];
            #pragma unroll
            for (int mt = 0; mt < 4; ++mt) {
                const unsigned* p = t1s + (wm * 64 + mt * 16 + g) * 68 + kc * 8 + t;
                a[mt][0] = p[0]; a[mt][1] = p[544]; a[mt][2] = p[4]; a[mt][3] = p[548];
            }
            #pragma unroll
            for (int nt = 0; nt < 4; ++nt) {
                int bi = ((wn * 4 + nt) * 8 + kc) * 32 + lane;
                uint2 bh = whu[bi];
                uint2 bl = wlu[bi];
                #pragma unroll
                for (int mt = 0; mt < 4; ++mt) {
                    mma16(acc2[mt][nt], a[mt][0], a[mt][1], a[mt][2], a[mt][3], bh.x, bh.y);
                    mma16(acc2[mt][nt], a[mt][0], a[mt][1], a[mt][2], a[mt][3], bl.x, bl.y);
                }
            }
        }

        // ---- segmented weighted pooling (batch sorted) ----
        float wv[4][2]; int sg[4][2];
        #pragma unroll
        for (int mt = 0; mt < 4; ++mt)
            #pragma unroll
            for (int i = 0; i < 2; ++i) {
                int r = wm * 64 + mt * 16 + g + 8 * i;
                wv[mt][i] = sew[r * 4 + wn];
                sg[mt][i] = sbat[r];
            }
        int s0 = sbat[wm * 64], s1 = sbat[wm * 64 + 63];
        for (int s = s0; s <= s1; ++s) {
            float p[8];
            #pragma unroll
            for (int v = 0; v < 8; ++v) p[v] = 0.f;
            #pragma unroll
            for (int mt = 0; mt < 4; ++mt)
                #pragma unroll
                for (int i = 0; i < 2; ++i)
                    if (sg[mt][i] == s) {
                        float w = wv[mt][i];
                        #pragma unroll
                        for (int nt = 0; nt < 4; ++nt) {
                            p[nt * 2]     = fmaf(w, acc2[mt][nt][i * 2],     p[nt * 2]);
                            p[nt * 2 + 1] = fmaf(w, acc2[mt][nt][i * 2 + 1], p[nt * 2 + 1]);
                        }
                    }
            #pragma unroll
            for (int off = 4; off <= 16; off <<= 1)
                #pragma unroll
                for (int v = 0; v < 8; ++v)
                    p[v] += __shfl_xor_sync(0xffffffffu, p[v], off);
            if (g == 0) {
                #pragma unroll
                for (int nt = 0; nt < 4; ++nt) {
                    atomicAdd(&out[(size_t)s * 128 + wn * 32 + nt * 8 + 2 * t],     p[nt * 2]);
                    atomicAdd(&out[(size_t)s * 128 + wn * 32 + nt * 8 + 2 * t + 1], p[nt * 2 + 1]);
                }
            }
        }
    }
}

// ------------------------------------------------------------------
// out = (pool + b2*D) / (D + 1e-16)
// ------------------------------------------------------------------
__global__ void k_div(float* __restrict__ out, const float* __restrict__ b2) {
    int i = blockIdx.x * blockDim.x + threadIdx.x;
    if (i < SEGS * 128) {
        int c = i & 127;
        float D = g_denom[(i >> 7) * 4 + (c >> 5)];
        out[i] = (out[i] + b2[c] * D) / (D + 1e-16f);
    }
}

// ------------------------------------------------------------------
extern "C" void kernel_launch(void* const* d_in, const int* in_sizes, int n_in,
                              void* d_out, int out_size)
{
    const float* x   = (const float*)d_in[0];
    const int*   bat = (const int*)d_in[1];
    // d_in[2] = num_segments (fixed 1024)
    const float* gw1 = (const float*)d_in[3];
    const float* pa  = (const float*)d_in[4];
    const float* gw2 = (const float*)d_in[5];
    const float* mw1 = (const float*)d_in[6];
    const float* mb1 = (const float*)d_in[7];
    const float* mw2 = (const float*)d_in[8];
    const float* mb2 = (const float*)d_in[9];
    float* out = (float*)d_out;

    int n = in_sizes[0] / 64;
    int nt64  = (n + 63) / 64;
    int nt128 = (n + 127) / 128;
    int sms = 148;
    cudaDeviceGetAttribute(&sms, cudaDevAttrMultiProcessorCount, 0);

    const int gate_smem = GATE_SMEM_W * 4;   // 54,528 B  (2 CTA/SM)
    const int feat_smem = FEAT_SMEM_W * 4;   // 138,240 B (1 CTA/SM)
    cudaFuncSetAttribute(k_gate, cudaFuncAttributeMaxDynamicSharedMemorySize, gate_smem);
    cudaFuncSetAttribute(k_feat, cudaFuncAttributeMaxDynamicSharedMemorySize, feat_smem);

    k_init<<<(SEGS * 128 + 255) / 256, 256>>>(out);
    k_gate<<<2 * sms, 256, gate_smem>>>(x, bat, gw1, gw2, pa, n, nt64);
    k_feat<<<sms, 256, feat_smem>>>(x, bat, mw1, mb1, mw2, out, n, nt128);
    k_div<<<(SEGS * 128 + 255) / 256, 256>>>(out, mb2);
}

// round 16
// speedup vs baseline: 4.8537x; 1.0124x over previous
#include <cuda_runtime.h>
#include <cuda_bf16.h>
#include <math.h>

#define SEGS 1024

// scratch (static device globals — no runtime allocation)
__device__ float g_gate[(size_t)500000 * 4];   // exp(gate)
__device__ float g_denom[SEGS * 4];

// pack two fp32 -> bf16x2 (lo -> low half, hi -> high half)
__device__ __forceinline__ unsigned packbf(float lo, float hi) {
    unsigned r;
    asm("cvt.rn.bf16x2.f32 %0, %1, %2;" : "=r"(r) : "f"(hi), "f"(lo));
    return r;
}

__device__ __forceinline__ void mma16(float c[4],
    unsigned a0, unsigned a1, unsigned a2, unsigned a3,
    unsigned b0, unsigned b1)
{
    asm volatile(
        "mma.sync.aligned.m16n8k16.row.col.f32.bf16.bf16.f32 "
        "{%0,%1,%2,%3},{%4,%5,%6,%7},{%8,%9},{%0,%1,%2,%3};"
        : "+f"(c[0]), "+f"(c[1]), "+f"(c[2]), "+f"(c[3])
        : "r"(a0), "r"(a1), "r"(a2), "r"(a3), "r"(b0), "r"(b1));
}

// pack W[outc][K] row-major -> bf16 B-fragment layout.
// uint2 per (nt, kc, lane): b0 = {W[n0+g][k0+2t], +1}, b1 = {W[n0+g][k0+2t+8], +9}
template<int K>
__device__ __forceinline__ void pack_b_bf(__nv_bfloat16* dst, const float4* src,
                                          int outc, int tid)
{
    const int K4 = K / 4, KCH = K / 16;
    for (int idx = tid; idx < outc * K4; idx += 256) {
        float4 v = src[idx];
        int n = idx / K4, q = idx % K4;
        int g = n & 7, nt = n >> 3;
        float vv[4] = {v.x, v.y, v.z, v.w};
        #pragma unroll
        for (int j = 0; j < 4; ++j) {
            int k = 4 * q + j;
            int kc = k >> 4, r = k & 15;
            int word = (((nt * KCH + kc) * 32) + g * 4 + ((r & 7) >> 1)) * 2 + (r >> 3);
            dst[word * 2 + (k & 1)] = __float2bfloat16(vv[j]);
        }
    }
}

// ------------------------------------------------------------------
__global__ void k_init(float* __restrict__ out) {
    int i = blockIdx.x * blockDim.x + threadIdx.x;
    if (i < SEGS * 128) out[i] = 0.f;
    if (i < SEGS * 4)   g_denom[i] = 0.f;
}

// ------------------------------------------------------------------
// k_gate: g_gate = exp(prelu(x@gw1^T)@gw2^T); denom += exp
// persistent, tile = 64 nodes, 8 warps (2m x 4n), warp tile 32x64
// projection onto 4 heads done with MMA (C-frag -> A-frag reuse)
// ------------------------------------------------------------------
// smem words: w1p 8192 | gw2p 1024 | xs 64*36=2304 | sgp 4*64*8=2048 | sbat 64
#define GATE_SMEM_W (8192 + 1024 + 2304 + 2048 + 64)
__global__ __launch_bounds__(256, 2) void k_gate(
    const float* __restrict__ x, const int* __restrict__ batch,
    const float* __restrict__ gw1, const float* __restrict__ gw2,
    const float* __restrict__ prelu_a, int n, int ntiles)
{
    extern __shared__ unsigned smw[];
    unsigned* w1p  = smw;                       // packed gw1 [256x64]
    unsigned* gw2p = smw + 8192;                // packed gw2 [8(pad)x256]
    unsigned* xs   = smw + 9216;                // x tile bf16 [64][36w]
    float*    sgp  = (float*)(smw + 11520);     // partial gate [4wn][64][8]
    int*      sbat = (int*)(smw + 13568);       // 64

    int tid = threadIdx.x;
    // weight packing (once per CTA)
    pack_b_bf<64>((__nv_bfloat16*)w1p, (const float4*)gw1, 256, tid);
    for (int i = tid; i < 1024; i += 256) gw2p[i] = 0;
    __syncthreads();
    {   // gw2 [4][256] -> B frags (heads 4..7 zero)
        const float4* g4 = (const float4*)gw2;
        __nv_bfloat16* dh = (__nv_bfloat16*)gw2p;
        if (tid < 256) {
            float4 v = g4[tid];
            int nn = tid >> 6, q = tid & 63;
            float vv[4] = {v.x, v.y, v.z, v.w};
            #pragma unroll
            for (int j = 0; j < 4; ++j) {
                int k = 4 * q + j;
                int kc = k >> 4, r = k & 15;
                int word = ((kc * 32) + nn * 4 + ((r & 7) >> 1)) * 2 + (r >> 3);
                dh[word * 2 + (k & 1)] = __float2bfloat16(vv[j]);
            }
        }
    }
    float slope = *prelu_a;

    int lane = tid & 31, g = lane >> 2, t = lane & 3;
    int wid = tid >> 5, wm = wid >> 2, wn = wid & 3;
    const uint2* w1u = (const uint2*)w1p;
    const uint2* g2u = (const uint2*)gw2p;

    for (int tile = blockIdx.x; tile < ntiles; tile += gridDim.x) {
        int m0 = tile * 64;
        __syncthreads();
        {   // x tile -> bf16
            const float4* x4 = (const float4*)x;
            #pragma unroll
            for (int i = 0; i < 4; ++i) {
                int fid = tid + i * 256, m = fid >> 4, q = fid & 15;
                float4 v = make_float4(0.f, 0.f, 0.f, 0.f);
                if (m0 + m < n) v = x4[(size_t)(m0 + m) * 16 + q];
                uint2 u; u.x = packbf(v.x, v.y); u.y = packbf(v.z, v.w);
                *(uint2*)(xs + m * 36 + q * 2) = u;
            }
            if (tid < 64) sbat[tid] = (m0 + tid < n) ? batch[m0 + tid] : batch[n - 1];
        }
        __syncthreads();

        float acc[2][8][4];
        #pragma unroll
        for (int a = 0; a < 2; ++a)
            #pragma unroll
            for (int b = 0; b < 8; ++b)
                #pragma unroll
                for (int c = 0; c < 4; ++c) acc[a][b][c] = 0.f;

        #pragma unroll
        for (int kc = 0; kc < 4; ++kc) {
            unsigned a[2][4];
            #pragma unroll
            for (int mt = 0; mt < 2; ++mt) {
                const unsigned* p = xs + (wm * 32 + mt * 16 + g) * 36 + kc * 8 + t;
                a[mt][0] = p[0]; a[mt][1] = p[288]; a[mt][2] = p[4]; a[mt][3] = p[292];
            }
            #pragma unroll
            for (int nt = 0; nt < 8; ++nt) {
                uint2 b = w1u[((wn * 8 + nt) * 4 + kc) * 32 + lane];
                #pragma unroll
                for (int mt = 0; mt < 2; ++mt)
                    mma16(acc[mt][nt], a[mt][0], a[mt][1], a[mt][2], a[mt][3], b.x, b.y);
            }
        }

        // PReLU + head projection via MMA (C frags become A frags)
        #pragma unroll
        for (int mt = 0; mt < 2; ++mt) {
            float pacc[4] = {0.f, 0.f, 0.f, 0.f};
            #pragma unroll
            for (int kcl = 0; kcl < 4; ++kcl) {
                int ne = 2 * kcl, no = ne + 1;
                float h[8];
                #pragma unroll
                for (int e = 0; e < 4; ++e) { h[e] = acc[mt][ne][e]; h[4 + e] = acc[mt][no][e]; }
                #pragma unroll
                for (int e = 0; e < 8; ++e) h[e] = fmaxf(h[e], 0.f) + slope * fminf(h[e], 0.f);
                unsigned a0 = packbf(h[0], h[1]), a1 = packbf(h[2], h[3]);
                unsigned a2 = packbf(h[4], h[5]), a3 = packbf(h[6], h[7]);
                uint2 b = g2u[(wn * 4 + kcl) * 32 + lane];
                mma16(pacc, a0, a1, a2, a3, b.x, b.y);
            }
            int row = wm * 32 + mt * 16 + g;
            *(float2*)&sgp[wn * 512 + row * 8 + 2 * t]       = make_float2(pacc[0], pacc[1]);
            *(float2*)&sgp[wn * 512 + (row + 8) * 8 + 2 * t] = make_float2(pacc[2], pacc[3]);
        }
        __syncthreads();

        {   // reduce over wn, exp, store, denom
            int row = tid >> 2, h = tid & 3;
            if (m0 + row < n) {
                float gs = sgp[row * 8 + h] + sgp[512 + row * 8 + h]
                         + sgp[1024 + row * 8 + h] + sgp[1536 + row * 8 + h];
                float w = expf(fminf(gs, 60.f));
                g_gate[(size_t)(m0 + row) * 4 + h] = w;
                atomicAdd(&g_denom[sbat[row] * 4 + h], w);
            }
        }
    }
}

// ------------------------------------------------------------------
// k_feat: feat = relu(x@mw1^T+b1)@(mw2hi+mw2lo)^T ; out[seg] += w*feat
// persistent, tile = 128 nodes, 8 warps (2m x 4n), warp tile 64x32
// ------------------------------------------------------------------
// words: w1p 4096 | w2h 8192 | w2l 8192 | xs 128*36=4608 | t1s 128*68=8704
//        sb1 128 | sew 512 | sbat 128
#define FEAT_SMEM_W (4096 + 8192 + 8192 + 4608 + 8704 + 128 + 512 + 128)
__global__ __launch_bounds__(256, 1) void k_feat(
    const float* __restrict__ x, const int* __restrict__ batch,
    const float* __restrict__ mw1, const float* __restrict__ mb1,
    const float* __restrict__ mw2, float* __restrict__ out, int n, int ntiles)
{
    extern __shared__ unsigned smw[];
    unsigned* w1p = smw;                      // packed mw1 [128x64]
    unsigned* w2h = smw + 4096;               // packed mw2 hi
    unsigned* w2l = smw + 12288;              // packed mw2 lo
    unsigned* xs  = smw + 20480;              // x tile bf16 [128][36w]
    unsigned* t1s = smw + 25088;              // t1 bf16 [128][68w]
    float*    sb1 = (float*)(smw + 33792);    // 128
    float*    sew = (float*)(smw + 33920);    // 512: exp(gate) [128][4]
    int*      sbat= (int*)(smw + 34432);      // 128

    int tid = threadIdx.x;
    pack_b_bf<64>((__nv_bfloat16*)w1p, (const float4*)mw1, 128, tid);
    {   // split-pack mw2: hi = bf16(w), lo = bf16(w - hi)
        const float4* src = (const float4*)mw2;
        __nv_bfloat16* dh = (__nv_bfloat16*)w2h;
        __nv_bfloat16* dl = (__nv_bfloat16*)w2l;
        for (int idx = tid; idx < 128 * 32; idx += 256) {
            float4 v = src[idx];
            int nn = idx >> 5, q = idx & 31;
            int g = nn & 7, nt = nn >> 3;
            float vv[4] = {v.x, v.y, v.z, v.w};
            #pragma unroll
            for (int j = 0; j < 4; ++j) {
                int k = 4 * q + j;
                int kc = k >> 4, r = k & 15;
                int hw = ((((nt * 8 + kc) * 32) + g * 4 + ((r & 7) >> 1)) * 2 + (r >> 3)) * 2 + (k & 1);
                __nv_bfloat16 hi = __float2bfloat16(vv[j]);
                dh[hw] = hi;
                dl[hw] = __float2bfloat16(vv[j] - __bfloat162float(hi));
            }
        }
    }
    for (int i = tid; i < 128; i += 256) sb1[i] = mb1[i];

    int lane = tid & 31, g = lane >> 2, t = lane & 3;
    int wid = tid >> 5, wm = wid >> 2, wn = wid & 3;
    const uint2* w1u = (const uint2*)w1p;
    const uint2* whu = (const uint2*)w2h;
    const uint2* wlu = (const uint2*)w2l;

    for (int tile = blockIdx.x; tile < ntiles; tile += gridDim.x) {
        int m0 = tile * 128;
        __syncthreads();
        {   // loads
            const float4* x4 = (const float4*)x;
            #pragma unroll
            for (int i = 0; i < 8; ++i) {
                int fid = tid + i * 256, m = fid >> 4, q = fid & 15;
                float4 v = make_float4(0.f, 0.f, 0.f, 0.f);
                if (m0 + m < n) v = x4[(size_t)(m0 + m) * 16 + q];
                uint2 u; u.x = packbf(v.x, v.y); u.y = packbf(v.z, v.w);
                *(uint2*)(xs + m * 36 + q * 2) = u;
            }
            #pragma unroll
            for (int i = 0; i < 2; ++i) {
                int e = tid + i * 256, m = e >> 2, h = e & 3;
                sew[e] = (m0 + m < n) ? g_gate[(size_t)(m0 + m) * 4 + h] : 0.f;
            }
            if (tid < 128) sbat[tid] = (m0 + tid < n) ? batch[m0 + tid] : batch[n - 1];
        }
        __syncthreads();

        // GEMM1: t1 = relu(x @ mw1^T + b1), K=64
        float acc1[4][4][4];
        #pragma unroll
        for (int a = 0; a < 4; ++a)
            #pragma unroll
            for (int b = 0; b < 4; ++b)
                #pragma unroll
                for (int c = 0; c < 4; ++c) acc1[a][b][c] = 0.f;

        #pragma unroll
        for (int kc = 0; kc < 4; ++kc) {
            unsigned a[4][4];
            #pragma unroll
            for (int mt = 0; mt < 4; ++mt) {
                const unsigned* p = xs + (wm * 64 + mt * 16 + g) * 36 + kc * 8 + t;
                a[mt][0] = p[0]; a[mt][1] = p[288]; a[mt][2] = p[4]; a[mt][3] = p[292];
            }
            #pragma unroll
            for (int nt = 0; nt < 4; ++nt) {
                uint2 b = w1u[((wn * 4 + nt) * 4 + kc) * 32 + lane];
                #pragma unroll
                for (int mt = 0; mt < 4; ++mt)
                    mma16(acc1[mt][nt], a[mt][0], a[mt][1], a[mt][2], a[mt][3], b.x, b.y);
            }
        }
        // bias + relu -> t1s (bf16 pairs, conflict-free)
        #pragma unroll
        for (int nt = 0; nt < 4; ++nt) {
            int c0 = wn * 32 + nt * 8 + 2 * t;
            float b0v = sb1[c0], b1v = sb1[c0 + 1];
            int cw = wn * 16 + nt * 4 + t;
            #pragma unroll
            for (int mt = 0; mt < 4; ++mt) {
                int row = wm * 64 + mt * 16 + g;
                t1s[row * 68 + cw] = packbf(fmaxf(acc1[mt][nt][0] + b0v, 0.f),
                                            fmaxf(acc1[mt][nt][1] + b1v, 0.f));
                t1s[(row + 8) * 68 + cw] = packbf(fmaxf(acc1[mt][nt][2] + b0v, 0.f),
                                                  fmaxf(acc1[mt][nt][3] + b1v, 0.f));
            }
        }
        __syncthreads();

        // GEMM2: feat = t1 @ mw2^T (split hi+lo), K=128
        float acc2[4][4][4];
        #pragma unroll
        for (int a = 0; a < 4; ++a)
            #pragma unroll
            for (int b = 0; b < 4; ++b)
                #pragma unroll
                for (int c = 0; c < 4; ++c) acc2[a][b][c] = 0.f;

        #pragma unroll
        for (int kc = 0; kc < 8; ++kc) {
            unsigned a[4][4];
            #pragma unroll
            for (int mt = 0; mt < 4; ++mt) {
                const unsigned* p = t1s + (wm * 64 + mt * 16 + g) * 68 + kc * 8 + t;
                a[mt][0] = p[0]; a[mt][1] = p[544]; a[mt][2] = p[4]; a[mt][3] = p[548];
            }
            #pragma unroll
            for (int nt = 0; nt < 4; ++nt) {
                int bi = ((wn * 4 + nt) * 8 + kc) * 32 + lane;
                uint2 bh = whu[bi];
                uint2 bl = wlu[bi];
                #pragma unroll
                for (int mt = 0; mt < 4; ++mt) {
                    mma16(acc2[mt][nt], a[mt][0], a[mt][1], a[mt][2], a[mt][3], bh.x, bh.y);
                    mma16(acc2[mt][nt], a[mt][0], a[mt][1], a[mt][2], a[mt][3], bl.x, bl.y);
                }
            }
        }

        // ---- segmented weighted pooling (batch sorted) ----
        float wv[4][2]; int sg[4][2];
        #pragma unroll
        for (int mt = 0; mt < 4; ++mt)
            #pragma unroll
            for (int i = 0; i < 2; ++i) {
                int r = wm * 64 + mt * 16 + g + 8 * i;
                wv[mt][i] = sew[r * 4 + wn];
                sg[mt][i] = sbat[r];
            }
        int s0 = sbat[wm * 64], s1 = sbat[wm * 64 + 63];
        for (int s = s0; s <= s1; ++s) {
            float p[8];
            #pragma unroll
            for (int v = 0; v < 8; ++v) p[v] = 0.f;
            #pragma unroll
            for (int mt = 0; mt < 4; ++mt)
                #pragma unroll
                for (int i = 0; i < 2; ++i)
                    if (sg[mt][i] == s) {
                        float w = wv[mt][i];
                        #pragma unroll
                        for (int nt = 0; nt < 4; ++nt) {
                            p[nt * 2]     = fmaf(w, acc2[mt][nt][i * 2],     p[nt * 2]);
                            p[nt * 2 + 1] = fmaf(w, acc2[mt][nt][i * 2 + 1], p[nt * 2 + 1]);
                        }
                    }
            #pragma unroll
            for (int off = 4; off <= 16; off <<= 1)
                #pragma unroll
                for (int v = 0; v < 8; ++v)
                    p[v] += __shfl_xor_sync(0xffffffffu, p[v], off);
            if (g == 0) {
                #pragma unroll
                for (int nt = 0; nt < 4; ++nt) {
                    atomicAdd(&out[(size_t)s * 128 + wn * 32 + nt * 8 + 2 * t],     p[nt * 2]);
                    atomicAdd(&out[(size_t)s * 128 + wn * 32 + nt * 8 + 2 * t + 1], p[nt * 2 + 1]);
                }
            }
        }
    }
}

// ------------------------------------------------------------------
// out = (pool + b2*D) / (D + 1e-16)
// ------------------------------------------------------------------
__global__ void k_div(float* __restrict__ out, const float* __restrict__ b2) {
    int i = blockIdx.x * blockDim.x + threadIdx.x;
    if (i < SEGS * 128) {
        int c = i & 127;
        float D = g_denom[(i >> 7) * 4 + (c >> 5)];
        out[i] = (out[i] + b2[c] * D) / (D + 1e-16f);
    }
}

// ------------------------------------------------------------------
extern "C" void kernel_launch(void* const* d_in, const int* in_sizes, int n_in,
                              void* d_out, int out_size)
{
    const float* x   = (const float*)d_in[0];
    const int*   bat = (const int*)d_in[1];
    // d_in[2] = num_segments (fixed 1024)
    const float* gw1 = (const float*)d_in[3];
    const float* pa  = (const float*)d_in[4];
    const float* gw2 = (const float*)d_in[5];
    const float* mw1 = (const float*)d_in[6];
    const float* mb1 = (const float*)d_in[7];
    const float* mw2 = (const float*)d_in[8];
    const float* mb2 = (const float*)d_in[9];
    float* out = (float*)d_out;

    int n = in_sizes[0] / 64;
    int nt64  = (n + 63) / 64;
    int nt128 = (n + 127) / 128;
    int sms = 148;
    cudaDeviceGetAttribute(&sms, cudaDevAttrMultiProcessorCount, 0);

    const int gate_smem = GATE_SMEM_W * 4;   // 54,528 B  (2 CTA/SM)
    const int feat_smem = FEAT_SMEM_W * 4;   // 138,240 B (1 CTA/SM)
    cudaFuncSetAttribute(k_gate, cudaFuncAttributeMaxDynamicSharedMemorySize, gate_smem);
    cudaFuncSetAttribute(k_feat, cudaFuncAttributeMaxDynamicSharedMemorySize, feat_smem);

    k_init<<<(SEGS * 128 + 255) / 256, 256>>>(out);
    k_gate<<<2 * sms, 256, gate_smem>>>(x, bat, gw1, gw2, pa, n, nt64);
    k_feat<<<sms, 256, feat_smem>>>(x, bat, mw1, mb1, mw2, out, n, nt128);
    k_div<<<(SEGS * 128 + 255) / 256, 256>>>(out, mb2);
}

// round 17
// speedup vs baseline: 6.1537x; 1.2678x over previous
#include <cuda_runtime.h>
#include <cuda_fp16.h>
#include <math.h>

#define SEGS 1024

__device__ float g_denom[SEGS * 4];

// pack two fp32 -> f16x2 (lo -> low half, hi -> high half)
__device__ __forceinline__ unsigned packhf(float lo, float hi) {
    unsigned r;
    asm("cvt.rn.f16x2.f32 %0, %1, %2;" : "=r"(r) : "f"(hi), "f"(lo));
    return r;
}

__device__ __forceinline__ void mma16(float c[4],
    unsigned a0, unsigned a1, unsigned a2, unsigned a3,
    unsigned b0, unsigned b1)
{
    asm volatile(
        "mma.sync.aligned.m16n8k16.row.col.f32.f16.f16.f32 "
        "{%0,%1,%2,%3},{%4,%5,%6,%7},{%8,%9},{%0,%1,%2,%3};"
        : "+f"(c[0]), "+f"(c[1]), "+f"(c[2]), "+f"(c[3])
        : "r"(a0), "r"(a1), "r"(a2), "r"(a3), "r"(b0), "r"(b1));
}

// pack W[outc][K] row-major -> fp16 B-fragment layout.
template<int K>
__device__ __forceinline__ void pack_b_hf(__half* dst, const float4* src,
                                          int outc, int tid)
{
    const int K4 = K / 4, KCH = K / 16;
    for (int idx = tid; idx < outc * K4; idx += 256) {
        float4 v = src[idx];
        int n = idx / K4, q = idx % K4;
        int g = n & 7, nt = n >> 3;
        float vv[4] = {v.x, v.y, v.z, v.w};
        #pragma unroll
        for (int j = 0; j < 4; ++j) {
            int k = 4 * q + j;
            int kc = k >> 4, r = k & 15;
            int word = (((nt * KCH + kc) * 32) + g * 4 + ((r & 7) >> 1)) * 2 + (r >> 3);
            dst[word * 2 + (k & 1)] = __float2half(vv[j]);
        }
    }
}

// ------------------------------------------------------------------
__global__ void k_init(float* __restrict__ out) {
    int i = blockIdx.x * blockDim.x + threadIdx.x;
    if (i < SEGS * 128) out[i] = 0.f;
    if (i < SEGS * 4)   g_denom[i] = 0.f;
}

// ------------------------------------------------------------------
// fused: w = exp(prelu(x@gw1^T)@gw2^T); feat = relu(x@mw1^T+b1)@mw2^T
//        out[seg] += w*feat ; denom[seg] += w
// persistent, tile = 128 nodes, 8 warps (2m x 4n)
// ------------------------------------------------------------------
// smem words: gw1p 8192 | gw2p 1024 | mw1p 4096 | mw2p 8192 |
//             xs 4608 | t1s 8704 | sgp 4096 | sb1 128 | sew 512 | sbat 128
#define FUSED_SMEM_W (8192 + 1024 + 4096 + 8192 + 4608 + 8704 + 4096 + 128 + 512 + 128)
__global__ __launch_bounds__(256, 1) void k_fused(
    const float* __restrict__ x, const int* __restrict__ batch,
    const float* __restrict__ gw1, const float* __restrict__ gw2,
    const float* __restrict__ prelu_a,
    const float* __restrict__ mw1, const float* __restrict__ mb1,
    const float* __restrict__ mw2, float* __restrict__ out, int n, int ntiles)
{
    extern __shared__ unsigned smw[];
    unsigned* gw1p = smw;                      // packed gw1 [256x64]
    unsigned* gw2p = smw + 8192;               // packed gw2 [8(pad)x256]
    unsigned* mw1p = smw + 9216;               // packed mw1 [128x64]
    unsigned* mw2p = smw + 13312;              // packed mw2 [128x128]
    unsigned* xs   = smw + 21504;              // x tile fp16 [128][36w]
    unsigned* t1s  = smw + 26112;              // t1 fp16 [128][68w]
    float*    sgp  = (float*)(smw + 34816);    // partial gate [4wn][128][8]
    float*    sb1  = (float*)(smw + 38912);    // 128
    float*    sew  = (float*)(smw + 39040);    // 512: exp(gate) [128][4]
    int*      sbat = (int*)(smw + 39552);      // 128

    int tid = threadIdx.x;
    // ---- one-time weight packing ----
    pack_b_hf<64>((__half*)gw1p, (const float4*)gw1, 256, tid);
    pack_b_hf<64>((__half*)mw1p, (const float4*)mw1, 128, tid);
    pack_b_hf<128>((__half*)mw2p, (const float4*)mw2, 128, tid);
    for (int i = tid; i < 1024; i += 256) gw2p[i] = 0;
    for (int i = tid; i < 128; i += 256) sb1[i] = mb1[i];
    __syncthreads();
    {   // gw2 [4][256] -> B frags (heads 4..7 zero)
        const float4* g4 = (const float4*)gw2;
        __half* dh = (__half*)gw2p;
        if (tid < 256) {
            float4 v = g4[tid];
            int nn = tid >> 6, q = tid & 63;
            float vv[4] = {v.x, v.y, v.z, v.w};
            #pragma unroll
            for (int j = 0; j < 4; ++j) {
                int k = 4 * q + j;
                int kc = k >> 4, r = k & 15;
                int word = ((kc * 32) + nn * 4 + ((r & 7) >> 1)) * 2 + (r >> 3);
                dh[word * 2 + (k & 1)] = __float2half(vv[j]);
            }
        }
    }
    float slope = *prelu_a;

    int lane = tid & 31, g = lane >> 2, t = lane & 3;
    int wid = tid >> 5, wm = wid >> 2, wn = wid & 3;
    const uint2* g1u = (const uint2*)gw1p;
    const uint2* g2u = (const uint2*)gw2p;
    const uint2* m1u = (const uint2*)mw1p;
    const uint2* m2u = (const uint2*)mw2p;

    for (int tile = blockIdx.x; tile < ntiles; tile += gridDim.x) {
        int m0 = tile * 128;
        __syncthreads();
        {   // loads: x tile -> fp16, sbat
            const float4* x4 = (const float4*)x;
            #pragma unroll
            for (int i = 0; i < 8; ++i) {
                int fid = tid + i * 256, m = fid >> 4, q = fid & 15;
                float4 v = make_float4(0.f, 0.f, 0.f, 0.f);
                if (m0 + m < n) v = x4[(size_t)(m0 + m) * 16 + q];
                uint2 u; u.x = packhf(v.x, v.y); u.y = packhf(v.z, v.w);
                *(uint2*)(xs + m * 36 + q * 2) = u;
            }
            if (tid < 128) sbat[tid] = (m0 + tid < n) ? batch[m0 + tid] : batch[n - 1];
        }
        __syncthreads();

        // ---- GATE: g = prelu(x@gw1^T)@gw2^T (proj via C->A frag reuse) ----
        #pragma unroll
        for (int mtg = 0; mtg < 2; ++mtg) {
            float gacc[2][8][4];
            #pragma unroll
            for (int a = 0; a < 2; ++a)
                #pragma unroll
                for (int b = 0; b < 8; ++b)
                    #pragma unroll
                    for (int c = 0; c < 4; ++c) gacc[a][b][c] = 0.f;

            #pragma unroll
            for (int kc = 0; kc < 4; ++kc) {
                unsigned a[2][4];
                #pragma unroll
                for (int mt = 0; mt < 2; ++mt) {
                    const unsigned* p = xs + (wm * 64 + (mtg * 2 + mt) * 16 + g) * 36 + kc * 8 + t;
                    a[mt][0] = p[0]; a[mt][1] = p[288]; a[mt][2] = p[4]; a[mt][3] = p[292];
                }
                #pragma unroll
                for (int nt = 0; nt < 8; ++nt) {
                    uint2 b = g1u[((wn * 8 + nt) * 4 + kc) * 32 + lane];
                    #pragma unroll
                    for (int mt = 0; mt < 2; ++mt)
                        mma16(gacc[mt][nt], a[mt][0], a[mt][1], a[mt][2], a[mt][3], b.x, b.y);
                }
            }
            // prelu + head projection
            #pragma unroll
            for (int mt = 0; mt < 2; ++mt) {
                float pacc[4] = {0.f, 0.f, 0.f, 0.f};
                #pragma unroll
                for (int kcl = 0; kcl < 4; ++kcl) {
                    int ne = 2 * kcl, no = ne + 1;
                    float h[8];
                    #pragma unroll
                    for (int e = 0; e < 4; ++e) { h[e] = gacc[mt][ne][e]; h[4 + e] = gacc[mt][no][e]; }
                    #pragma unroll
                    for (int e = 0; e < 8; ++e) h[e] = fmaxf(h[e], 0.f) + slope * fminf(h[e], 0.f);
                    unsigned a0 = packhf(h[0], h[1]), a1 = packhf(h[2], h[3]);
                    unsigned a2 = packhf(h[4], h[5]), a3 = packhf(h[6], h[7]);
                    uint2 b = g2u[(wn * 4 + kcl) * 32 + lane];
                    mma16(pacc, a0, a1, a2, a3, b.x, b.y);
                }
                int row = wm * 64 + (mtg * 2 + mt) * 16 + g;
                *(float2*)&sgp[wn * 1024 + row * 8 + 2 * t]       = make_float2(pacc[0], pacc[1]);
                *(float2*)&sgp[wn * 1024 + (row + 8) * 8 + 2 * t] = make_float2(pacc[2], pacc[3]);
            }
        }
        __syncthreads();

        {   // reduce over wn, exp -> sew, denom REDG
            #pragma unroll
            for (int i = 0; i < 2; ++i) {
                int e = tid + i * 256;          // < 512
                int row = e >> 2, h = e & 3;
                float gs = sgp[row * 8 + h] + sgp[1024 + row * 8 + h]
                         + sgp[2048 + row * 8 + h] + sgp[3072 + row * 8 + h];
                if (m0 + row < n) {
                    float w = expf(fminf(gs, 60.f));
                    sew[e] = w;
                    atomicAdd(&g_denom[sbat[row] * 4 + h], w);
                } else sew[e] = 0.f;
            }
        }

        // ---- GEMM1: t1 = relu(x @ mw1^T + b1), K=64 ----
        float acc1[4][4][4];
        #pragma unroll
        for (int a = 0; a < 4; ++a)
            #pragma unroll
            for (int b = 0; b < 4; ++b)
                #pragma unroll
                for (int c = 0; c < 4; ++c) acc1[a][b][c] = 0.f;

        #pragma unroll
        for (int kc = 0; kc < 4; ++kc) {
            unsigned a[4][4];
            #pragma unroll
            for (int mt = 0; mt < 4; ++mt) {
                const unsigned* p = xs + (wm * 64 + mt * 16 + g) * 36 + kc * 8 + t;
                a[mt][0] = p[0]; a[mt][1] = p[288]; a[mt][2] = p[4]; a[mt][3] = p[292];
            }
            #pragma unroll
            for (int nt = 0; nt < 4; ++nt) {
                uint2 b = m1u[((wn * 4 + nt) * 4 + kc) * 32 + lane];
                #pragma unroll
                for (int mt = 0; mt < 4; ++mt)
                    mma16(acc1[mt][nt], a[mt][0], a[mt][1], a[mt][2], a[mt][3], b.x, b.y);
            }
        }
        // bias + relu -> t1s (fp16 pairs)
        #pragma unroll
        for (int nt = 0; nt < 4; ++nt) {
            int c0 = wn * 32 + nt * 8 + 2 * t;
            float b0v = sb1[c0], b1v = sb1[c0 + 1];
            int cw = wn * 16 + nt * 4 + t;
            #pragma unroll
            for (int mt = 0; mt < 4; ++mt) {
                int row = wm * 64 + mt * 16 + g;
                t1s[row * 68 + cw] = packhf(fmaxf(acc1[mt][nt][0] + b0v, 0.f),
                                            fmaxf(acc1[mt][nt][1] + b1v, 0.f));
                t1s[(row + 8) * 68 + cw] = packhf(fmaxf(acc1[mt][nt][2] + b0v, 0.f),
                                                  fmaxf(acc1[mt][nt][3] + b1v, 0.f));
            }
        }
        __syncthreads();

        // ---- GEMM2: feat = t1 @ mw2^T (single fp16), K=128 ----
        float acc2[4][4][4];
        #pragma unroll
        for (int a = 0; a < 4; ++a)
            #pragma unroll
            for (int b = 0; b < 4; ++b)
                #pragma unroll
                for (int c = 0; c < 4; ++c) acc2[a][b][c] = 0.f;

        #pragma unroll
        for (int kc = 0; kc < 8; ++kc) {
            unsigned a[4][4];
            #pragma unroll
            for (int mt = 0; mt < 4; ++mt) {
                const unsigned* p = t1s + (wm * 64 + mt * 16 + g) * 68 + kc * 8 + t;
                a[mt][0] = p[0]; a[mt][1] = p[544]; a[mt][2] = p[4]; a[mt][3] = p[548];
            }
            #pragma unroll
            for (int nt = 0; nt < 4; ++nt) {
                uint2 b = m2u[((wn * 4 + nt) * 8 + kc) * 32 + lane];
                #pragma unroll
                for (int mt = 0; mt < 4; ++mt)
                    mma16(acc2[mt][nt], a[mt][0], a[mt][1], a[mt][2], a[mt][3], b.x, b.y);
            }
        }

        // ---- segmented weighted pooling (batch sorted) ----
        float wv[4][2]; int sg[4][2];
        #pragma unroll
        for (int mt = 0; mt < 4; ++mt)
            #pragma unroll
            for (int i = 0; i < 2; ++i) {
                int r = wm * 64 + mt * 16 + g + 8 * i;
                wv[mt][i] = sew[r * 4 + wn];
                sg[mt][i] = sbat[r];
            }
        int s0 = sbat[wm * 64], s1 = sbat[wm * 64 + 63];
        for (int s = s0; s <= s1; ++s) {
            float p[8];
            #pragma unroll
            for (int v = 0; v < 8; ++v) p[v] = 0.f;
            #pragma unroll
            for (int mt = 0; mt < 4; ++mt)
                #pragma unroll
                for (int i = 0; i < 2; ++i)
                    if (sg[mt][i] == s) {
                        float w = wv[mt][i];
                        #pragma unroll
                        for (int nt = 0; nt < 4; ++nt) {
                            p[nt * 2]     = fmaf(w, acc2[mt][nt][i * 2],     p[nt * 2]);
                            p[nt * 2 + 1] = fmaf(w, acc2[mt][nt][i * 2 + 1], p[nt * 2 + 1]);
                        }
                    }
            #pragma unroll
            for (int off = 4; off <= 16; off <<= 1)
                #pragma unroll
                for (int v = 0; v < 8; ++v)
                    p[v] += __shfl_xor_sync(0xffffffffu, p[v], off);
            if (g == 0) {
                #pragma unroll
                for (int nt = 0; nt < 4; ++nt) {
                    atomicAdd(&out[(size_t)s * 128 + wn * 32 + nt * 8 + 2 * t],     p[nt * 2]);
                    atomicAdd(&out[(size_t)s * 128 + wn * 32 + nt * 8 + 2 * t + 1], p[nt * 2 + 1]);
                }
            }
        }
    }
}

// ------------------------------------------------------------------
// out = (pool + b2*D) / (D + 1e-16)
// ------------------------------------------------------------------
__global__ void k_div(float* __restrict__ out, const float* __restrict__ b2) {
    int i = blockIdx.x * blockDim.x + threadIdx.x;
    if (i < SEGS * 128) {
        int c = i & 127;
        float D = g_denom[(i >> 7) * 4 + (c >> 5)];
        out[i] = (out[i] + b2[c] * D) / (D + 1e-16f);
    }
}

// ------------------------------------------------------------------
extern "C" void kernel_launch(void* const* d_in, const int* in_sizes, int n_in,
                              void* d_out, int out_size)
{
    const float* x   = (const float*)d_in[0];
    const int*   bat = (const int*)d_in[1];
    // d_in[2] = num_segments (fixed 1024)
    const float* gw1 = (const float*)d_in[3];
    const float* pa  = (const float*)d_in[4];
    const float* gw2 = (const float*)d_in[5];
    const float* mw1 = (const float*)d_in[6];
    const float* mb1 = (const float*)d_in[7];
    const float* mw2 = (const float*)d_in[8];
    const float* mb2 = (const float*)d_in[9];
    float* out = (float*)d_out;

    int n = in_sizes[0] / 64;
    int ntiles = (n + 127) / 128;
    int sms = 148;
    cudaDeviceGetAttribute(&sms, cudaDevAttrMultiProcessorCount, 0);

    const int fused_smem = FUSED_SMEM_W * 4;   // 158,720 B (1 CTA/SM)
    cudaFuncSetAttribute(k_fused, cudaFuncAttributeMaxDynamicSharedMemorySize, fused_smem);

    k_init<<<(SEGS * 128 + 255) / 256, 256>>>(out);
    k_fused<<<sms, 256, fused_smem>>>(x, bat, gw1, gw2, pa, mw1, mb1, mw2, out, n, ntiles);
    k_div<<<(SEGS * 128 + 255) / 256, 256>>>(out, mb2);
}